// round 5
// baseline (speedup 1.0000x reference)
#include <cuda_runtime.h>
#include <stdint.h>

// Problem constants
#define N_SRC0 200000
#define N_DST0 50000
#define N_DST1 10000
#define NE0    800000
#define NE1    160000
#define DIM    256
#define NBASE  4
#define BD     64
#define NPAIR  5000
#define NPTOT  (2 * NPAIR)

// ---------------------------------------------------------------------------
// Scratch (__device__ globals; kernels reference them directly)
// ---------------------------------------------------------------------------
__device__ float g_agg0[(size_t)N_DST0 * DIM];
__device__ float g_agg1[(size_t)N_DST1 * DIM];
__device__ float g_h0  [(size_t)N_DST0 * DIM];
__device__ float g_h1  [(size_t)N_DST1 * DIM];

__device__ __align__(16) int g_cnt0[N_DST0];
__device__ __align__(16) int g_cnt1[N_DST1];
__device__ int g_rowptr0[N_DST0 + 1];
__device__ int g_rowptr1[N_DST1 + 1];
__device__ int g_cur0[N_DST0];
__device__ int g_cur1[N_DST1];
__device__ int g_esrc0[NE0];
__device__ int g_esrc1[NE1];

// ---------------------------------------------------------------------------
// Zero the per-dst edge counters
// ---------------------------------------------------------------------------
__global__ void zero_cnt_kernel() {
    int stride = gridDim.x * blockDim.x;
    int i0 = blockIdx.x * blockDim.x + threadIdx.x;
    for (int i = i0; i < N_DST0; i += stride) g_cnt0[i] = 0;
    for (int i = i0; i < N_DST1; i += stride) g_cnt1[i] = 0;
}

// ---------------------------------------------------------------------------
// CSR build: count, scan, fill
// ---------------------------------------------------------------------------
template <int WHICH>
__global__ void count_kernel(const int* __restrict__ dst, int ne) {
    int* cnt = WHICH ? g_cnt1 : g_cnt0;
    int e = blockIdx.x * blockDim.x + threadIdx.x;
    if (e < ne) atomicAdd(&cnt[dst[e]], 1);
}

// Single-block exclusive scan, 8 elements per thread (8192-wide tiles).
template <int WHICH>
__global__ __launch_bounds__(1024) void scan_kernel() {
    const int* cnt = WHICH ? g_cnt1 : g_cnt0;
    int* rowptr    = WHICH ? g_rowptr1 : g_rowptr0;
    int* cur       = WHICH ? g_cur1 : g_cur0;
    const int n    = WHICH ? N_DST1 : N_DST0;
    const int VT   = 8;
    const int TILE = 1024 * VT;

    __shared__ int wsum[32];
    __shared__ int s_carry, s_bt;
    int tid = threadIdx.x, lane = tid & 31, wid = tid >> 5;
    if (tid == 0) s_carry = 0;
    __syncthreads();

    for (int base = 0; base < n; base += TILE) {
        int idx0 = base + tid * VT;
        int v[VT];
        if (idx0 + VT <= n) {
            int4 a = *(const int4*)(cnt + idx0);
            int4 b = *(const int4*)(cnt + idx0 + 4);
            v[0]=a.x; v[1]=a.y; v[2]=a.z; v[3]=a.w;
            v[4]=b.x; v[5]=b.y; v[6]=b.z; v[7]=b.w;
        } else {
            #pragma unroll
            for (int j = 0; j < VT; ++j) v[j] = (idx0 + j < n) ? cnt[idx0 + j] : 0;
        }
        int incl[VT]; int s = 0;
        #pragma unroll
        for (int j = 0; j < VT; ++j) { s += v[j]; incl[j] = s; }
        int tot = s;
        int wincl = tot;
        #pragma unroll
        for (int o = 1; o < 32; o <<= 1) {
            int t = __shfl_up_sync(0xFFFFFFFFu, wincl, o);
            if (lane >= o) wincl += t;
        }
        if (lane == 31) wsum[wid] = wincl;
        __syncthreads();
        if (wid == 0) {
            int w = wsum[lane];
            int wi = w;
            #pragma unroll
            for (int o = 1; o < 32; o <<= 1) {
                int t = __shfl_up_sync(0xFFFFFFFFu, wi, o);
                if (lane >= o) wi += t;
            }
            wsum[lane] = wi - w;           // exclusive warp offsets
            if (lane == 31) s_bt = wi;     // tile total
        }
        __syncthreads();
        int myexcl = s_carry + wsum[wid] + (wincl - tot);
        #pragma unroll
        for (int j = 0; j < VT; ++j) {
            int i = idx0 + j;
            if (i < n) {
                int e = myexcl + incl[j] - v[j];
                rowptr[i] = e;
                cur[i] = e;
            }
        }
        __syncthreads();                   // all reads of s_carry done
        if (tid == 0) s_carry += s_bt;
        __syncthreads();
    }
    if (tid == 0) rowptr[n] = s_carry;
}

template <int WHICH>
__global__ void fill_kernel(const int* __restrict__ src,
                            const int* __restrict__ dst, int ne) {
    int* cur  = WHICH ? g_cur1 : g_cur0;
    int* esrc = WHICH ? g_esrc1 : g_esrc0;
    int e = blockIdx.x * blockDim.x + threadIdx.x;
    if (e < ne) {
        int p = atomicAdd(&cur[dst[e]], 1);
        esrc[p] = src[e];
    }
}

// ---------------------------------------------------------------------------
// Pull-mode aggregation: agg[d, :] = sum over edges of feat[src, :]
// 128 threads per block = 2 dst rows, 64 threads (float4 each) per row.
// ---------------------------------------------------------------------------
template <int WHICH>
__global__ __launch_bounds__(128) void gather_kernel(const float* __restrict__ featp) {
    const float* feat  = WHICH ? g_h0 : featp;
    float* agg         = WHICH ? g_agg1 : g_agg0;
    const int* rowptr  = WHICH ? g_rowptr1 : g_rowptr0;
    const int* esrc    = WHICH ? g_esrc1 : g_esrc0;
    const int ndst     = WHICH ? N_DST1 : N_DST0;

    int d = blockIdx.x * 2 + (threadIdx.x >> 6);
    int lane = threadIdx.x & 63;
    if (d >= ndst) return;

    int beg = rowptr[d], end = rowptr[d + 1];
    float4 acc = make_float4(0.f, 0.f, 0.f, 0.f);
    const float4* f4 = (const float4*)feat;

    int i = beg;
    for (; i + 1 < end; i += 2) {
        int s0 = esrc[i], s1 = esrc[i + 1];
        float4 v0 = f4[(size_t)s0 * (DIM / 4) + lane];
        float4 v1 = f4[(size_t)s1 * (DIM / 4) + lane];
        acc.x += v0.x + v1.x; acc.y += v0.y + v1.y;
        acc.z += v0.z + v1.z; acc.w += v0.w + v1.w;
    }
    if (i < end) {
        int s0 = esrc[i];
        float4 v0 = f4[(size_t)s0 * (DIM / 4) + lane];
        acc.x += v0.x; acc.y += v0.y; acc.z += v0.z; acc.w += v0.w;
    }
    ((float4*)agg)[(size_t)d * (DIM / 4) + lane] = acc;
}

// ---------------------------------------------------------------------------
// tf32 tensor-core fused layer GEMM.
// Block tile 128x64, 256 threads (8 warps, 4x2 warp grid, 32x32 per warp).
// grid = (NBASE, ceil(M/128)); cb = blockIdx.x so the 4 column blocks
// sharing one row tile are schedule-adjacent (xd re-read hits L2).
// ---------------------------------------------------------------------------
__device__ __forceinline__ uint32_t f32_to_tf32(float f) {
    uint32_t u;
    asm("cvt.rna.tf32.f32 %0, %1;" : "=r"(u) : "f"(f));
    return u;
}

template <int LAYER>
__global__ __launch_bounds__(256) void layer_kernel(
    const float* __restrict__ xparam, // layer0: x; layer1 unused
    const float* __restrict__ W,      // [4,64,64]
    const float* __restrict__ loopw,  // [256,256]
    const float* __restrict__ bias,   // [256]
    float*       __restrict__ out2,   // optional mirror (may be null)
    int M)
{
    const float* agg = (LAYER == 0) ? g_agg0 : g_agg1;
    const float* xd  = (LAYER == 0) ? xparam : g_h0;
    float*       out = (LAYER == 0) ? g_h0   : g_h1;

    __shared__ uint32_t As[128][36];   // 128 rows x 32 k (pad 36)
    __shared__ uint32_t Bs[32][72];    // 32 k x 64 n (pad 72)

    const int cb  = blockIdx.x;        // output column block (0..3)
    const int r0  = blockIdx.y * 128;
    const int tid = threadIdx.x;
    const int lane = tid & 31;
    const int w   = tid >> 5;          // warp 0..7
    const int wm  = w & 3;             // warp row (4)
    const int wn  = w >> 2;            // warp col (2)
    const int t4  = lane >> 2;         // 0..7
    const int tc  = lane & 3;          // 0..3

    float acc[2][4][4];
    #pragma unroll
    for (int mt = 0; mt < 2; ++mt)
        #pragma unroll
        for (int nt = 0; nt < 4; ++nt)
            #pragma unroll
            for (int i = 0; i < 4; ++i) acc[mt][nt][i] = 0.f;

    for (int ch = 0; ch < 10; ++ch) {
        const float* amat = (ch < 8) ? xd : agg;
        const int akbase  = (ch < 8) ? ch * 32 : cb * 64 + (ch - 8) * 32;

        // ---- load A tile: 128x32, 4 float4 per thread ----
        float4 av[4];
        #pragma unroll
        for (int l = 0; l < 4; ++l) {
            int idx = tid + l * 256;        // 0..1023
            int row = idx >> 3;             // /8 (8 float4 per row)
            int c4  = idx & 7;
            av[l] = make_float4(0.f, 0.f, 0.f, 0.f);
            if (r0 + row < M)
                av[l] = *(const float4*)(amat + (size_t)(r0 + row) * DIM + akbase + c4 * 4);
        }
        // ---- load B tile: 32x64, 2 float4 per thread ----
        float4 bv[2];
        #pragma unroll
        for (int l = 0; l < 2; ++l) {
            int idx = tid + l * 256;        // 0..511
            int row = idx >> 4;             // /16 (16 float4 per row)
            int c4  = idx & 15;
            if (ch < 8)
                bv[l] = *(const float4*)(loopw + (size_t)(ch * 32 + row) * DIM + cb * 64 + c4 * 4);
            else
                bv[l] = *(const float4*)(W + (size_t)cb * BD * BD
                                           + (size_t)((ch - 8) * 32 + row) * BD + c4 * 4);
        }

        __syncthreads();   // previous chunk compute done

        #pragma unroll
        for (int l = 0; l < 4; ++l) {
            int idx = tid + l * 256;
            int row = idx >> 3;
            int c4  = idx & 7;
            As[row][c4 * 4 + 0] = f32_to_tf32(av[l].x);
            As[row][c4 * 4 + 1] = f32_to_tf32(av[l].y);
            As[row][c4 * 4 + 2] = f32_to_tf32(av[l].z);
            As[row][c4 * 4 + 3] = f32_to_tf32(av[l].w);
        }
        #pragma unroll
        for (int l = 0; l < 2; ++l) {
            int idx = tid + l * 256;
            int row = idx >> 4;
            int c4  = idx & 15;
            Bs[row][c4 * 4 + 0] = f32_to_tf32(bv[l].x);
            Bs[row][c4 * 4 + 1] = f32_to_tf32(bv[l].y);
            Bs[row][c4 * 4 + 2] = f32_to_tf32(bv[l].z);
            Bs[row][c4 * 4 + 3] = f32_to_tf32(bv[l].w);
        }
        __syncthreads();

        // ---- compute: 4 k-steps of 8 ----
        #pragma unroll
        for (int k0 = 0; k0 < 32; k0 += 8) {
            uint32_t a[2][4];
            #pragma unroll
            for (int mt = 0; mt < 2; ++mt) {
                int mrow = wm * 32 + mt * 16 + t4;
                a[mt][0] = As[mrow][k0 + tc];
                a[mt][1] = As[mrow + 8][k0 + tc];
                a[mt][2] = As[mrow][k0 + tc + 4];
                a[mt][3] = As[mrow + 8][k0 + tc + 4];
            }
            #pragma unroll
            for (int nt = 0; nt < 4; ++nt) {
                int ncol = wn * 32 + nt * 8 + t4;
                uint32_t b0 = Bs[k0 + tc][ncol];
                uint32_t b1 = Bs[k0 + tc + 4][ncol];
                #pragma unroll
                for (int mt = 0; mt < 2; ++mt) {
                    asm volatile(
                        "mma.sync.aligned.m16n8k8.row.col.f32.tf32.tf32.f32 "
                        "{%0,%1,%2,%3}, {%4,%5,%6,%7}, {%8,%9}, {%0,%1,%2,%3};\n"
                        : "+f"(acc[mt][nt][0]), "+f"(acc[mt][nt][1]),
                          "+f"(acc[mt][nt][2]), "+f"(acc[mt][nt][3])
                        : "r"(a[mt][0]), "r"(a[mt][1]), "r"(a[mt][2]), "r"(a[mt][3]),
                          "r"(b0), "r"(b1));
                }
            }
        }
        __syncthreads();
    }

    // ---- epilogue: bias + relu, float2 stores ----
    #pragma unroll
    for (int nt = 0; nt < 4; ++nt) {
        int c = cb * 64 + wn * 32 + nt * 8 + 2 * tc;
        float2 bb = *(const float2*)(bias + c);
        #pragma unroll
        for (int mt = 0; mt < 2; ++mt) {
            int r = r0 + wm * 32 + mt * 16 + t4;
            if (r < M) {
                float2 o;
                o.x = fmaxf(acc[mt][nt][0] + bb.x, 0.f);
                o.y = fmaxf(acc[mt][nt][1] + bb.y, 0.f);
                *(float2*)(out + (size_t)r * DIM + c) = o;
                if (out2) *(float2*)(out2 + (size_t)r * DIM + c) = o;
            }
            if (r + 8 < M) {
                float2 o;
                o.x = fmaxf(acc[mt][nt][2] + bb.x, 0.f);
                o.y = fmaxf(acc[mt][nt][3] + bb.y, 0.f);
                *(float2*)(out + (size_t)(r + 8) * DIM + c) = o;
                if (out2) *(float2*)(out2 + (size_t)(r + 8) * DIM + c) = o;
            }
        }
    }
}

// ---------------------------------------------------------------------------
// Link predictor, batched: 32 pairs per 128-thread block.
// Stage E rows (h[a]*h[b]) in smem, register-block over pairs so pw1 is
// streamed once per block (40 MB total vs 1.28 GB for per-pair blocks).
// ---------------------------------------------------------------------------
#define PPB 32
__global__ __launch_bounds__(128) void pred_kernel(
    const int*   __restrict__ ps, const int* __restrict__ pd,
    const int*   __restrict__ ns, const int* __restrict__ nd,
    const float* __restrict__ pw1,    // [256, 128]
    const float* __restrict__ pb1,    // [128]
    const float* __restrict__ pw2,    // [128]
    const float* __restrict__ pb2,    // [1]
    float*       __restrict__ out)    // [10000] : pos then neg
{
    const float* h = g_h1;
    __shared__ float es[PPB][256];
    __shared__ int   sa[PPB], sb[PPB];
    __shared__ float s_part[4][PPB];

    int tid  = threadIdx.x;           // 0..127
    int lane = tid & 31;
    int wid  = tid >> 5;
    int pbase = blockIdx.x * PPB;

    if (tid < PPB) {
        int P = pbase + tid;
        int a = 0, b = 0;
        if (P < NPTOT) {
            if (P < NPAIR) { a = ps[P]; b = pd[P]; }
            else           { a = ns[P - NPAIR]; b = nd[P - NPAIR]; }
        }
        sa[tid] = a; sb[tid] = b;
    }
    __syncthreads();

    #pragma unroll 4
    for (int p = 0; p < PPB; ++p) {
        int a = sa[p], b = sb[p];
        es[p][tid]       = h[(size_t)a * DIM + tid]       * h[(size_t)b * DIM + tid];
        es[p][tid + 128] = h[(size_t)a * DIM + 128 + tid] * h[(size_t)b * DIM + 128 + tid];
    }
    __syncthreads();

    float acc[PPB];
    #pragma unroll
    for (int p = 0; p < PPB; ++p) acc[p] = 0.f;

    for (int j = 0; j < 256; j += 4) {
        float w0 = pw1[(j + 0) * 128 + tid];
        float w1 = pw1[(j + 1) * 128 + tid];
        float w2 = pw1[(j + 2) * 128 + tid];
        float w3 = pw1[(j + 3) * 128 + tid];
        #pragma unroll
        for (int p = 0; p < PPB; ++p) {
            float4 e4 = *(const float4*)&es[p][j];
            acc[p] += e4.x * w0 + e4.y * w1 + e4.z * w2 + e4.w * w3;
        }
    }

    float pb  = pb1[tid];
    float w2v = pw2[tid];
    #pragma unroll
    for (int p = 0; p < PPB; ++p) {
        float v = fmaxf(acc[p] + pb, 0.f) * w2v;
        #pragma unroll
        for (int o = 16; o; o >>= 1) v += __shfl_xor_sync(0xFFFFFFFFu, v, o);
        if (lane == 0) s_part[wid][p] = v;
    }
    __syncthreads();
    if (tid < PPB) {
        int P = pbase + tid;
        if (P < NPTOT)
            out[P] = s_part[0][tid] + s_part[1][tid] + s_part[2][tid] + s_part[3][tid]
                   + pb2[0];
    }
}

// ---------------------------------------------------------------------------
// Launch
// ---------------------------------------------------------------------------
extern "C" void kernel_launch(void* const* d_in, const int* in_sizes, int n_in,
                              void* d_out, int out_size)
{
    const float* x     = (const float*)d_in[0];
    const int*   src0  = (const int*)d_in[1];
    const int*   dst0  = (const int*)d_in[2];
    const int*   src1  = (const int*)d_in[3];
    const int*   dst1  = (const int*)d_in[4];
    const int*   psrc  = (const int*)d_in[5];
    const int*   pdst  = (const int*)d_in[6];
    const int*   nsrc  = (const int*)d_in[7];
    const int*   ndst  = (const int*)d_in[8];
    const float* W0    = (const float*)d_in[9];
    const float* loop0 = (const float*)d_in[10];
    const float* b0    = (const float*)d_in[11];
    const float* W1    = (const float*)d_in[12];
    const float* loop1 = (const float*)d_in[13];
    const float* b1    = (const float*)d_in[14];
    const float* pw1   = (const float*)d_in[15];
    const float* pb1   = (const float*)d_in[16];
    const float* pw2   = (const float*)d_in[17];
    const float* pb2   = (const float*)d_in[18];
    float*       out   = (float*)d_out;

    // CSR build for both layers
    zero_cnt_kernel<<<256, 256>>>();
    count_kernel<0><<<(NE0 + 255) / 256, 256>>>(dst0, NE0);
    count_kernel<1><<<(NE1 + 255) / 256, 256>>>(dst1, NE1);
    scan_kernel<0><<<1, 1024>>>();
    scan_kernel<1><<<1, 1024>>>();
    fill_kernel<0><<<(NE0 + 255) / 256, 256>>>(src0, dst0, NE0);
    fill_kernel<1><<<(NE1 + 255) / 256, 256>>>(src1, dst1, NE1);

    // layer 0: pull-aggregate x, fused tf32 transform -> h0
    gather_kernel<0><<<(N_DST0 + 1) / 2, 128>>>(x);
    {
        dim3 grid(NBASE, (N_DST0 + 127) / 128);
        layer_kernel<0><<<grid, 256>>>(x, W0, loop0, b0, nullptr, N_DST0);
    }

    // layer 1: pull-aggregate h0, fused transform -> h1 (+mirror to out)
    gather_kernel<1><<<(N_DST1 + 1) / 2, 128>>>(nullptr);
    {
        dim3 grid(NBASE, (N_DST1 + 127) / 128);
        layer_kernel<1><<<grid, 256>>>(nullptr, W1, loop1, b1,
                                       out + NPTOT, N_DST1);
    }

    // link prediction -> out[0:5000] (pos), out[5000:10000] (neg)
    pred_kernel<<<(NPTOT + PPB - 1) / PPB, 128>>>(psrc, pdst, nsrc, ndst,
                                                  pw1, pb1, pw2, pb2, out);
}

// round 6
// speedup vs baseline: 1.0086x; 1.0086x over previous
#include <cuda_runtime.h>
#include <stdint.h>

// Problem constants
#define N_SRC0 200000
#define N_DST0 50000
#define N_DST1 10000
#define NE0    800000
#define NE1    160000
#define DIM    256
#define NBASE  4
#define BD     64
#define NPAIR  5000
#define NPTOT  (2 * NPAIR)

// ---------------------------------------------------------------------------
// Scratch (__device__ globals; kernels reference them directly)
// ---------------------------------------------------------------------------
__device__ float g_agg0[(size_t)N_DST0 * DIM];
__device__ float g_agg1[(size_t)N_DST1 * DIM];
__device__ float g_h0  [(size_t)N_DST0 * DIM];
__device__ float g_h1  [(size_t)N_DST1 * DIM];

__device__ __align__(16) int g_cnt0[N_DST0];
__device__ __align__(16) int g_cnt1[N_DST1];
__device__ int g_rowptr0[N_DST0 + 1];
__device__ int g_rowptr1[N_DST1 + 1];
__device__ int g_cur0[N_DST0];
__device__ int g_cur1[N_DST1];
__device__ int g_esrc0[NE0];
__device__ int g_esrc1[NE1];

// ---------------------------------------------------------------------------
// Zero the per-dst edge counters
// ---------------------------------------------------------------------------
__global__ void zero_cnt_kernel() {
    int stride = gridDim.x * blockDim.x;
    int i0 = blockIdx.x * blockDim.x + threadIdx.x;
    for (int i = i0; i < N_DST0; i += stride) g_cnt0[i] = 0;
    for (int i = i0; i < N_DST1; i += stride) g_cnt1[i] = 0;
}

// ---------------------------------------------------------------------------
// CSR build: count, scan, fill
// ---------------------------------------------------------------------------
template <int WHICH>
__global__ void count_kernel(const int* __restrict__ dst, int ne) {
    int* cnt = WHICH ? g_cnt1 : g_cnt0;
    int e = blockIdx.x * blockDim.x + threadIdx.x;
    if (e < ne) atomicAdd(&cnt[dst[e]], 1);
}

// Single-block exclusive scan, 8 elements per thread (8192-wide tiles).
template <int WHICH>
__global__ __launch_bounds__(1024) void scan_kernel() {
    const int* cnt = WHICH ? g_cnt1 : g_cnt0;
    int* rowptr    = WHICH ? g_rowptr1 : g_rowptr0;
    int* cur       = WHICH ? g_cur1 : g_cur0;
    const int n    = WHICH ? N_DST1 : N_DST0;
    const int VT   = 8;
    const int TILE = 1024 * VT;

    __shared__ int wsum[32];
    __shared__ int s_carry, s_bt;
    int tid = threadIdx.x, lane = tid & 31, wid = tid >> 5;
    if (tid == 0) s_carry = 0;
    __syncthreads();

    for (int base = 0; base < n; base += TILE) {
        int idx0 = base + tid * VT;
        int v[VT];
        if (idx0 + VT <= n) {
            int4 a = *(const int4*)(cnt + idx0);
            int4 b = *(const int4*)(cnt + idx0 + 4);
            v[0]=a.x; v[1]=a.y; v[2]=a.z; v[3]=a.w;
            v[4]=b.x; v[5]=b.y; v[6]=b.z; v[7]=b.w;
        } else {
            #pragma unroll
            for (int j = 0; j < VT; ++j) v[j] = (idx0 + j < n) ? cnt[idx0 + j] : 0;
        }
        int incl[VT]; int s = 0;
        #pragma unroll
        for (int j = 0; j < VT; ++j) { s += v[j]; incl[j] = s; }
        int tot = s;
        int wincl = tot;
        #pragma unroll
        for (int o = 1; o < 32; o <<= 1) {
            int t = __shfl_up_sync(0xFFFFFFFFu, wincl, o);
            if (lane >= o) wincl += t;
        }
        if (lane == 31) wsum[wid] = wincl;
        __syncthreads();
        if (wid == 0) {
            int w = wsum[lane];
            int wi = w;
            #pragma unroll
            for (int o = 1; o < 32; o <<= 1) {
                int t = __shfl_up_sync(0xFFFFFFFFu, wi, o);
                if (lane >= o) wi += t;
            }
            wsum[lane] = wi - w;           // exclusive warp offsets
            if (lane == 31) s_bt = wi;     // tile total
        }
        __syncthreads();
        int myexcl = s_carry + wsum[wid] + (wincl - tot);
        #pragma unroll
        for (int j = 0; j < VT; ++j) {
            int i = idx0 + j;
            if (i < n) {
                int e = myexcl + incl[j] - v[j];
                rowptr[i] = e;
                cur[i] = e;
            }
        }
        __syncthreads();                   // all reads of s_carry done
        if (tid == 0) s_carry += s_bt;
        __syncthreads();
    }
    if (tid == 0) rowptr[n] = s_carry;
}

template <int WHICH>
__global__ void fill_kernel(const int* __restrict__ src,
                            const int* __restrict__ dst, int ne) {
    int* cur  = WHICH ? g_cur1 : g_cur0;
    int* esrc = WHICH ? g_esrc1 : g_esrc0;
    int e = blockIdx.x * blockDim.x + threadIdx.x;
    if (e < ne) {
        int p = atomicAdd(&cur[dst[e]], 1);
        esrc[p] = src[e];
    }
}

// ---------------------------------------------------------------------------
// Pull-mode aggregation: agg[d, :] = sum over edges of feat[src, :]
// 128 threads per block = 2 dst rows, 64 threads (float4 each) per row.
// ---------------------------------------------------------------------------
template <int WHICH>
__global__ __launch_bounds__(128) void gather_kernel(const float* __restrict__ featp) {
    const float* feat  = WHICH ? g_h0 : featp;
    float* agg         = WHICH ? g_agg1 : g_agg0;
    const int* rowptr  = WHICH ? g_rowptr1 : g_rowptr0;
    const int* esrc    = WHICH ? g_esrc1 : g_esrc0;
    const int ndst     = WHICH ? N_DST1 : N_DST0;

    int d = blockIdx.x * 2 + (threadIdx.x >> 6);
    int lane = threadIdx.x & 63;
    if (d >= ndst) return;

    int beg = rowptr[d], end = rowptr[d + 1];
    float4 acc = make_float4(0.f, 0.f, 0.f, 0.f);
    const float4* f4 = (const float4*)feat;

    int i = beg;
    for (; i + 1 < end; i += 2) {
        int s0 = esrc[i], s1 = esrc[i + 1];
        float4 v0 = f4[(size_t)s0 * (DIM / 4) + lane];
        float4 v1 = f4[(size_t)s1 * (DIM / 4) + lane];
        acc.x += v0.x + v1.x; acc.y += v0.y + v1.y;
        acc.z += v0.z + v1.z; acc.w += v0.w + v1.w;
    }
    if (i < end) {
        int s0 = esrc[i];
        float4 v0 = f4[(size_t)s0 * (DIM / 4) + lane];
        acc.x += v0.x; acc.y += v0.y; acc.z += v0.z; acc.w += v0.w;
    }
    ((float4*)agg)[(size_t)d * (DIM / 4) + lane] = acc;
}

// ---------------------------------------------------------------------------
// tf32 tensor-core fused layer GEMM.
// Block tile 128x64, 256 threads (8 warps, 4x2 warp grid, 32x32 per warp).
// grid = (NBASE, ceil(M/128)); cb = blockIdx.x so the 4 column blocks
// sharing one row tile are schedule-adjacent (xd re-read hits L2).
// ---------------------------------------------------------------------------
__device__ __forceinline__ uint32_t f32_to_tf32(float f) {
    uint32_t u;
    asm("cvt.rna.tf32.f32 %0, %1;" : "=r"(u) : "f"(f));
    return u;
}

template <int LAYER>
__global__ __launch_bounds__(256) void layer_kernel(
    const float* __restrict__ xparam, // layer0: x; layer1 unused
    const float* __restrict__ W,      // [4,64,64]
    const float* __restrict__ loopw,  // [256,256]
    const float* __restrict__ bias,   // [256]
    float*       __restrict__ out2,   // optional mirror (may be null)
    int M)
{
    const float* agg = (LAYER == 0) ? g_agg0 : g_agg1;
    const float* xd  = (LAYER == 0) ? xparam : g_h0;
    float*       out = (LAYER == 0) ? g_h0   : g_h1;

    __shared__ uint32_t As[128][36];   // 128 rows x 32 k (pad 36)
    __shared__ uint32_t Bs[32][72];    // 32 k x 64 n (pad 72)

    const int cb  = blockIdx.x;        // output column block (0..3)
    const int r0  = blockIdx.y * 128;
    const int tid = threadIdx.x;
    const int lane = tid & 31;
    const int w   = tid >> 5;          // warp 0..7
    const int wm  = w & 3;             // warp row (4)
    const int wn  = w >> 2;            // warp col (2)
    const int t4  = lane >> 2;         // 0..7
    const int tc  = lane & 3;          // 0..3

    float acc[2][4][4];
    #pragma unroll
    for (int mt = 0; mt < 2; ++mt)
        #pragma unroll
        for (int nt = 0; nt < 4; ++nt)
            #pragma unroll
            for (int i = 0; i < 4; ++i) acc[mt][nt][i] = 0.f;

    for (int ch = 0; ch < 10; ++ch) {
        const float* amat = (ch < 8) ? xd : agg;
        const int akbase  = (ch < 8) ? ch * 32 : cb * 64 + (ch - 8) * 32;

        // ---- load A tile: 128x32, 4 float4 per thread ----
        float4 av[4];
        #pragma unroll
        for (int l = 0; l < 4; ++l) {
            int idx = tid + l * 256;        // 0..1023
            int row = idx >> 3;             // /8 (8 float4 per row)
            int c4  = idx & 7;
            av[l] = make_float4(0.f, 0.f, 0.f, 0.f);
            if (r0 + row < M)
                av[l] = *(const float4*)(amat + (size_t)(r0 + row) * DIM + akbase + c4 * 4);
        }
        // ---- load B tile: 32x64, 2 float4 per thread ----
        float4 bv[2];
        #pragma unroll
        for (int l = 0; l < 2; ++l) {
            int idx = tid + l * 256;        // 0..511
            int row = idx >> 4;             // /16 (16 float4 per row)
            int c4  = idx & 15;
            if (ch < 8)
                bv[l] = *(const float4*)(loopw + (size_t)(ch * 32 + row) * DIM + cb * 64 + c4 * 4);
            else
                bv[l] = *(const float4*)(W + (size_t)cb * BD * BD
                                           + (size_t)((ch - 8) * 32 + row) * BD + c4 * 4);
        }

        __syncthreads();   // previous chunk compute done

        #pragma unroll
        for (int l = 0; l < 4; ++l) {
            int idx = tid + l * 256;
            int row = idx >> 3;
            int c4  = idx & 7;
            As[row][c4 * 4 + 0] = f32_to_tf32(av[l].x);
            As[row][c4 * 4 + 1] = f32_to_tf32(av[l].y);
            As[row][c4 * 4 + 2] = f32_to_tf32(av[l].z);
            As[row][c4 * 4 + 3] = f32_to_tf32(av[l].w);
        }
        #pragma unroll
        for (int l = 0; l < 2; ++l) {
            int idx = tid + l * 256;
            int row = idx >> 4;
            int c4  = idx & 15;
            Bs[row][c4 * 4 + 0] = f32_to_tf32(bv[l].x);
            Bs[row][c4 * 4 + 1] = f32_to_tf32(bv[l].y);
            Bs[row][c4 * 4 + 2] = f32_to_tf32(bv[l].z);
            Bs[row][c4 * 4 + 3] = f32_to_tf32(bv[l].w);
        }
        __syncthreads();

        // ---- compute: 4 k-steps of 8 ----
        #pragma unroll
        for (int k0 = 0; k0 < 32; k0 += 8) {
            uint32_t a[2][4];
            #pragma unroll
            for (int mt = 0; mt < 2; ++mt) {
                int mrow = wm * 32 + mt * 16 + t4;
                a[mt][0] = As[mrow][k0 + tc];
                a[mt][1] = As[mrow + 8][k0 + tc];
                a[mt][2] = As[mrow][k0 + tc + 4];
                a[mt][3] = As[mrow + 8][k0 + tc + 4];
            }
            #pragma unroll
            for (int nt = 0; nt < 4; ++nt) {
                int ncol = wn * 32 + nt * 8 + t4;
                uint32_t b0 = Bs[k0 + tc][ncol];
                uint32_t b1 = Bs[k0 + tc + 4][ncol];
                #pragma unroll
                for (int mt = 0; mt < 2; ++mt) {
                    asm volatile(
                        "mma.sync.aligned.m16n8k8.row.col.f32.tf32.tf32.f32 "
                        "{%0,%1,%2,%3}, {%4,%5,%6,%7}, {%8,%9}, {%0,%1,%2,%3};\n"
                        : "+f"(acc[mt][nt][0]), "+f"(acc[mt][nt][1]),
                          "+f"(acc[mt][nt][2]), "+f"(acc[mt][nt][3])
                        : "r"(a[mt][0]), "r"(a[mt][1]), "r"(a[mt][2]), "r"(a[mt][3]),
                          "r"(b0), "r"(b1));
                }
            }
        }
        __syncthreads();
    }

    // ---- epilogue: bias + relu, float2 stores ----
    #pragma unroll
    for (int nt = 0; nt < 4; ++nt) {
        int c = cb * 64 + wn * 32 + nt * 8 + 2 * tc;
        float2 bb = *(const float2*)(bias + c);
        #pragma unroll
        for (int mt = 0; mt < 2; ++mt) {
            int r = r0 + wm * 32 + mt * 16 + t4;
            if (r < M) {
                float2 o;
                o.x = fmaxf(acc[mt][nt][0] + bb.x, 0.f);
                o.y = fmaxf(acc[mt][nt][1] + bb.y, 0.f);
                *(float2*)(out + (size_t)r * DIM + c) = o;
                if (out2) *(float2*)(out2 + (size_t)r * DIM + c) = o;
            }
            if (r + 8 < M) {
                float2 o;
                o.x = fmaxf(acc[mt][nt][2] + bb.x, 0.f);
                o.y = fmaxf(acc[mt][nt][3] + bb.y, 0.f);
                *(float2*)(out + (size_t)(r + 8) * DIM + c) = o;
                if (out2) *(float2*)(out2 + (size_t)(r + 8) * DIM + c) = o;
            }
        }
    }
}

// ---------------------------------------------------------------------------
// Link predictor, batched: 32 pairs per 128-thread block.
// Stage E rows (h[a]*h[b]) in smem, register-block over pairs so pw1 is
// streamed once per block (40 MB total vs 1.28 GB for per-pair blocks).
// ---------------------------------------------------------------------------
#define PPB 32
__global__ __launch_bounds__(128) void pred_kernel(
    const int*   __restrict__ ps, const int* __restrict__ pd,
    const int*   __restrict__ ns, const int* __restrict__ nd,
    const float* __restrict__ pw1,    // [256, 128]
    const float* __restrict__ pb1,    // [128]
    const float* __restrict__ pw2,    // [128]
    const float* __restrict__ pb2,    // [1]
    float*       __restrict__ out)    // [10000] : pos then neg
{
    const float* h = g_h1;
    __shared__ float es[PPB][256];
    __shared__ int   sa[PPB], sb[PPB];
    __shared__ float s_part[4][PPB];

    int tid  = threadIdx.x;           // 0..127
    int lane = tid & 31;
    int wid  = tid >> 5;
    int pbase = blockIdx.x * PPB;

    if (tid < PPB) {
        int P = pbase + tid;
        int a = 0, b = 0;
        if (P < NPTOT) {
            if (P < NPAIR) { a = ps[P]; b = pd[P]; }
            else           { a = ns[P - NPAIR]; b = nd[P - NPAIR]; }
        }
        sa[tid] = a; sb[tid] = b;
    }
    __syncthreads();

    #pragma unroll 4
    for (int p = 0; p < PPB; ++p) {
        int a = sa[p], b = sb[p];
        es[p][tid]       = h[(size_t)a * DIM + tid]       * h[(size_t)b * DIM + tid];
        es[p][tid + 128] = h[(size_t)a * DIM + 128 + tid] * h[(size_t)b * DIM + 128 + tid];
    }
    __syncthreads();

    float acc[PPB];
    #pragma unroll
    for (int p = 0; p < PPB; ++p) acc[p] = 0.f;

    for (int j = 0; j < 256; j += 4) {
        float w0 = pw1[(j + 0) * 128 + tid];
        float w1 = pw1[(j + 1) * 128 + tid];
        float w2 = pw1[(j + 2) * 128 + tid];
        float w3 = pw1[(j + 3) * 128 + tid];
        #pragma unroll
        for (int p = 0; p < PPB; ++p) {
            float4 e4 = *(const float4*)&es[p][j];
            acc[p] += e4.x * w0 + e4.y * w1 + e4.z * w2 + e4.w * w3;
        }
    }

    float pb  = pb1[tid];
    float w2v = pw2[tid];
    #pragma unroll
    for (int p = 0; p < PPB; ++p) {
        float v = fmaxf(acc[p] + pb, 0.f) * w2v;
        #pragma unroll
        for (int o = 16; o; o >>= 1) v += __shfl_xor_sync(0xFFFFFFFFu, v, o);
        if (lane == 0) s_part[wid][p] = v;
    }
    __syncthreads();
    if (tid < PPB) {
        int P = pbase + tid;
        if (P < NPTOT)
            out[P] = s_part[0][tid] + s_part[1][tid] + s_part[2][tid] + s_part[3][tid]
                   + pb2[0];
    }
}

// ---------------------------------------------------------------------------
// Launch
// ---------------------------------------------------------------------------
extern "C" void kernel_launch(void* const* d_in, const int* in_sizes, int n_in,
                              void* d_out, int out_size)
{
    const float* x     = (const float*)d_in[0];
    const int*   src0  = (const int*)d_in[1];
    const int*   dst0  = (const int*)d_in[2];
    const int*   src1  = (const int*)d_in[3];
    const int*   dst1  = (const int*)d_in[4];
    const int*   psrc  = (const int*)d_in[5];
    const int*   pdst  = (const int*)d_in[6];
    const int*   nsrc  = (const int*)d_in[7];
    const int*   ndst  = (const int*)d_in[8];
    const float* W0    = (const float*)d_in[9];
    const float* loop0 = (const float*)d_in[10];
    const float* b0    = (const float*)d_in[11];
    const float* W1    = (const float*)d_in[12];
    const float* loop1 = (const float*)d_in[13];
    const float* b1    = (const float*)d_in[14];
    const float* pw1   = (const float*)d_in[15];
    const float* pb1   = (const float*)d_in[16];
    const float* pw2   = (const float*)d_in[17];
    const float* pb2   = (const float*)d_in[18];
    float*       out   = (float*)d_out;

    // CSR build for both layers
    zero_cnt_kernel<<<256, 256>>>();
    count_kernel<0><<<(NE0 + 255) / 256, 256>>>(dst0, NE0);
    count_kernel<1><<<(NE1 + 255) / 256, 256>>>(dst1, NE1);
    scan_kernel<0><<<1, 1024>>>();
    scan_kernel<1><<<1, 1024>>>();
    fill_kernel<0><<<(NE0 + 255) / 256, 256>>>(src0, dst0, NE0);
    fill_kernel<1><<<(NE1 + 255) / 256, 256>>>(src1, dst1, NE1);

    // layer 0: pull-aggregate x, fused tf32 transform -> h0
    gather_kernel<0><<<(N_DST0 + 1) / 2, 128>>>(x);
    {
        dim3 grid(NBASE, (N_DST0 + 127) / 128);
        layer_kernel<0><<<grid, 256>>>(x, W0, loop0, b0, nullptr, N_DST0);
    }

    // layer 1: pull-aggregate h0, fused transform -> h1 (+mirror to out)
    gather_kernel<1><<<(N_DST1 + 1) / 2, 128>>>(nullptr);
    {
        dim3 grid(NBASE, (N_DST1 + 127) / 128);
        layer_kernel<1><<<grid, 256>>>(nullptr, W1, loop1, b1,
                                       out + NPTOT, N_DST1);
    }

    // link prediction -> out[0:5000] (pos), out[5000:10000] (neg)
    pred_kernel<<<(NPTOT + PPB - 1) / PPB, 128>>>(psrc, pdst, nsrc, ndst,
                                                  pw1, pb1, pw2, pb2, out);
}

// round 7
// speedup vs baseline: 1.1745x; 1.1645x over previous
#include <cuda_runtime.h>
#include <stdint.h>

// Problem constants
#define N_SRC0 200000
#define N_DST0 50000
#define N_DST1 10000
#define NE0    800000
#define NE1    160000
#define DIM    256
#define NBASE  4
#define BD     64
#define NPAIR  5000
#define NPTOT  (2 * NPAIR)

#define SCAN_CHUNK 4096
#define NBLK0 ((N_DST0 + SCAN_CHUNK - 1) / SCAN_CHUNK)   // 13
#define NBLK1 ((N_DST1 + SCAN_CHUNK - 1) / SCAN_CHUNK)   // 3

// ---------------------------------------------------------------------------
// Scratch (__device__ globals; kernels reference them directly)
// ---------------------------------------------------------------------------
__device__ float g_agg0[(size_t)N_DST0 * DIM];
__device__ float g_agg1[(size_t)N_DST1 * DIM];
__device__ float g_h0  [(size_t)N_DST0 * DIM];
__device__ float g_h1  [(size_t)N_DST1 * DIM];

__device__ __align__(16) int g_cnt0[N_DST0];
__device__ __align__(16) int g_cnt1[N_DST1];
__device__ __align__(16) int g_rowptr0[N_DST0 + 1];
__device__ __align__(16) int g_rowptr1[N_DST1 + 1];
__device__ __align__(16) int g_cur0[N_DST0];
__device__ __align__(16) int g_cur1[N_DST1];
__device__ int g_esrc0[NE0];
__device__ int g_esrc1[NE1];
__device__ int g_part0[NBLK0];
__device__ int g_part1[NBLK1];

// ---------------------------------------------------------------------------
// Zero the per-dst edge counters
// ---------------------------------------------------------------------------
__global__ void zero_cnt_kernel() {
    int stride = gridDim.x * blockDim.x;
    int i0 = blockIdx.x * blockDim.x + threadIdx.x;
    for (int i = i0; i < N_DST0; i += stride) g_cnt0[i] = 0;
    for (int i = i0; i < N_DST1; i += stride) g_cnt1[i] = 0;
}

// ---------------------------------------------------------------------------
// CSR build: count, hierarchical scan (2 phases), fill
// ---------------------------------------------------------------------------
template <int WHICH>
__global__ void count_kernel(const int* __restrict__ dst, int ne) {
    int* cnt = WHICH ? g_cnt1 : g_cnt0;
    int e = blockIdx.x * blockDim.x + threadIdx.x;
    if (e < ne) atomicAdd(&cnt[dst[e]], 1);
}

// Phase A: each block exclusive-scans a 4096-element chunk (local offsets only)
// and records its chunk total. 512 threads x 8 elems.
template <int WHICH>
__global__ __launch_bounds__(512) void scan_a_kernel() {
    const int* cnt = WHICH ? g_cnt1 : g_cnt0;
    int* rowptr    = WHICH ? g_rowptr1 : g_rowptr0;
    int* part      = WHICH ? g_part1 : g_part0;
    const int n    = WHICH ? N_DST1 : N_DST0;

    __shared__ int wsum[16];
    const int tid  = threadIdx.x;
    const int lane = tid & 31;
    const int wid  = tid >> 5;            // 0..15
    const int base = blockIdx.x * SCAN_CHUNK;
    const int idx0 = base + tid * 8;

    int v[8];
    if (idx0 + 8 <= n) {
        int4 a = *(const int4*)(cnt + idx0);
        int4 b = *(const int4*)(cnt + idx0 + 4);
        v[0]=a.x; v[1]=a.y; v[2]=a.z; v[3]=a.w;
        v[4]=b.x; v[5]=b.y; v[6]=b.z; v[7]=b.w;
    } else {
        #pragma unroll
        for (int j = 0; j < 8; ++j) v[j] = (idx0 + j < n) ? cnt[idx0 + j] : 0;
    }
    int incl[8]; int tot = 0;
    #pragma unroll
    for (int j = 0; j < 8; ++j) { tot += v[j]; incl[j] = tot; }

    int wincl = tot;
    #pragma unroll
    for (int o = 1; o < 32; o <<= 1) {
        int t = __shfl_up_sync(0xFFFFFFFFu, wincl, o);
        if (lane >= o) wincl += t;
    }
    if (lane == 31) wsum[wid] = wincl;
    __syncthreads();
    if (tid == 0) {
        int running = 0;
        #pragma unroll
        for (int w = 0; w < 16; ++w) { int t = wsum[w]; wsum[w] = running; running += t; }
        part[blockIdx.x] = running;
    }
    __syncthreads();

    int myexcl = wsum[wid] + (wincl - tot);
    if (idx0 + 8 <= n) {
        int4 r0 = make_int4(myexcl + incl[0]-v[0], myexcl + incl[1]-v[1],
                            myexcl + incl[2]-v[2], myexcl + incl[3]-v[3]);
        int4 r1 = make_int4(myexcl + incl[4]-v[4], myexcl + incl[5]-v[5],
                            myexcl + incl[6]-v[6], myexcl + incl[7]-v[7]);
        *(int4*)(rowptr + idx0)     = r0;
        *(int4*)(rowptr + idx0 + 4) = r1;
    } else {
        #pragma unroll
        for (int j = 0; j < 8; ++j)
            if (idx0 + j < n) rowptr[idx0 + j] = myexcl + incl[j] - v[j];
    }
}

// Phase B: each block adds the sum of preceding chunk totals, mirrors to cur.
template <int WHICH>
__global__ __launch_bounds__(512) void scan_b_kernel() {
    int* rowptr    = WHICH ? g_rowptr1 : g_rowptr0;
    int* cur       = WHICH ? g_cur1 : g_cur0;
    const int* part= WHICH ? g_part1 : g_part0;
    const int n    = WHICH ? N_DST1 : N_DST0;
    const int nblk = WHICH ? NBLK1 : NBLK0;

    const int b = blockIdx.x;
    int off = 0;
    for (int k = 0; k < b; ++k) off += part[k];   // <=12 broadcast loads

    const int tid  = threadIdx.x;
    const int idx0 = b * SCAN_CHUNK + tid * 8;
    if (idx0 + 8 <= n) {
        int4 a = *(const int4*)(rowptr + idx0);
        int4 c = *(const int4*)(rowptr + idx0 + 4);
        a.x += off; a.y += off; a.z += off; a.w += off;
        c.x += off; c.y += off; c.z += off; c.w += off;
        *(int4*)(rowptr + idx0)     = a;
        *(int4*)(rowptr + idx0 + 4) = c;
        *(int4*)(cur + idx0)        = a;
        *(int4*)(cur + idx0 + 4)    = c;
    } else {
        #pragma unroll
        for (int j = 0; j < 8; ++j) {
            int i = idx0 + j;
            if (i < n) { int e = rowptr[i] + off; rowptr[i] = e; cur[i] = e; }
        }
    }
    if (b == nblk - 1 && tid == 0) rowptr[n] = off + part[b];
}

template <int WHICH>
__global__ void fill_kernel(const int* __restrict__ src,
                            const int* __restrict__ dst, int ne) {
    int* cur  = WHICH ? g_cur1 : g_cur0;
    int* esrc = WHICH ? g_esrc1 : g_esrc0;
    int e = blockIdx.x * blockDim.x + threadIdx.x;
    if (e < ne) {
        int p = atomicAdd(&cur[dst[e]], 1);
        esrc[p] = src[e];
    }
}

// ---------------------------------------------------------------------------
// Pull-mode aggregation: agg[d, :] = sum over edges of feat[src, :]
// 128 threads per block = 2 dst rows, 64 threads (float4 each) per row.
// ---------------------------------------------------------------------------
template <int WHICH>
__global__ __launch_bounds__(128) void gather_kernel(const float* __restrict__ featp) {
    const float* feat  = WHICH ? g_h0 : featp;
    float* agg         = WHICH ? g_agg1 : g_agg0;
    const int* rowptr  = WHICH ? g_rowptr1 : g_rowptr0;
    const int* esrc    = WHICH ? g_esrc1 : g_esrc0;
    const int ndst     = WHICH ? N_DST1 : N_DST0;

    int d = blockIdx.x * 2 + (threadIdx.x >> 6);
    int lane = threadIdx.x & 63;
    if (d >= ndst) return;

    int beg = rowptr[d], end = rowptr[d + 1];
    float4 acc = make_float4(0.f, 0.f, 0.f, 0.f);
    const float4* f4 = (const float4*)feat;

    int i = beg;
    for (; i + 1 < end; i += 2) {
        int s0 = esrc[i], s1 = esrc[i + 1];
        float4 v0 = f4[(size_t)s0 * (DIM / 4) + lane];
        float4 v1 = f4[(size_t)s1 * (DIM / 4) + lane];
        acc.x += v0.x + v1.x; acc.y += v0.y + v1.y;
        acc.z += v0.z + v1.z; acc.w += v0.w + v1.w;
    }
    if (i < end) {
        int s0 = esrc[i];
        float4 v0 = f4[(size_t)s0 * (DIM / 4) + lane];
        acc.x += v0.x; acc.y += v0.y; acc.z += v0.z; acc.w += v0.w;
    }
    ((float4*)agg)[(size_t)d * (DIM / 4) + lane] = acc;
}

// ---------------------------------------------------------------------------
// tf32 tensor-core fused layer GEMM.
// Block tile 128x64, 256 threads (8 warps, 4x2 warp grid, 32x32 per warp).
// ---------------------------------------------------------------------------
__device__ __forceinline__ uint32_t f32_to_tf32(float f) {
    uint32_t u;
    asm("cvt.rna.tf32.f32 %0, %1;" : "=r"(u) : "f"(f));
    return u;
}

template <int LAYER>
__global__ __launch_bounds__(256) void layer_kernel(
    const float* __restrict__ xparam, // layer0: x; layer1 unused
    const float* __restrict__ W,      // [4,64,64]
    const float* __restrict__ loopw,  // [256,256]
    const float* __restrict__ bias,   // [256]
    float*       __restrict__ out2,   // optional mirror (may be null)
    int M)
{
    const float* agg = (LAYER == 0) ? g_agg0 : g_agg1;
    const float* xd  = (LAYER == 0) ? xparam : g_h0;
    float*       out = (LAYER == 0) ? g_h0   : g_h1;

    __shared__ uint32_t As[128][36];   // 128 rows x 32 k (pad 36)
    __shared__ uint32_t Bs[32][72];    // 32 k x 64 n (pad 72)

    const int cb  = blockIdx.x;        // output column block (0..3)
    const int r0  = blockIdx.y * 128;
    const int tid = threadIdx.x;
    const int lane = tid & 31;
    const int w   = tid >> 5;          // warp 0..7
    const int wm  = w & 3;             // warp row (4)
    const int wn  = w >> 2;            // warp col (2)
    const int t4  = lane >> 2;         // 0..7
    const int tc  = lane & 3;          // 0..3

    float acc[2][4][4];
    #pragma unroll
    for (int mt = 0; mt < 2; ++mt)
        #pragma unroll
        for (int nt = 0; nt < 4; ++nt)
            #pragma unroll
            for (int i = 0; i < 4; ++i) acc[mt][nt][i] = 0.f;

    for (int ch = 0; ch < 10; ++ch) {
        const float* amat = (ch < 8) ? xd : agg;
        const int akbase  = (ch < 8) ? ch * 32 : cb * 64 + (ch - 8) * 32;

        // ---- load A tile: 128x32, 4 float4 per thread ----
        float4 av[4];
        #pragma unroll
        for (int l = 0; l < 4; ++l) {
            int idx = tid + l * 256;        // 0..1023
            int row = idx >> 3;             // /8 (8 float4 per row)
            int c4  = idx & 7;
            av[l] = make_float4(0.f, 0.f, 0.f, 0.f);
            if (r0 + row < M)
                av[l] = *(const float4*)(amat + (size_t)(r0 + row) * DIM + akbase + c4 * 4);
        }
        // ---- load B tile: 32x64, 2 float4 per thread ----
        float4 bv[2];
        #pragma unroll
        for (int l = 0; l < 2; ++l) {
            int idx = tid + l * 256;        // 0..511
            int row = idx >> 4;             // /16 (16 float4 per row)
            int c4  = idx & 15;
            if (ch < 8)
                bv[l] = *(const float4*)(loopw + (size_t)(ch * 32 + row) * DIM + cb * 64 + c4 * 4);
            else
                bv[l] = *(const float4*)(W + (size_t)cb * BD * BD
                                           + (size_t)((ch - 8) * 32 + row) * BD + c4 * 4);
        }

        __syncthreads();   // previous chunk compute done

        #pragma unroll
        for (int l = 0; l < 4; ++l) {
            int idx = tid + l * 256;
            int row = idx >> 3;
            int c4  = idx & 7;
            As[row][c4 * 4 + 0] = f32_to_tf32(av[l].x);
            As[row][c4 * 4 + 1] = f32_to_tf32(av[l].y);
            As[row][c4 * 4 + 2] = f32_to_tf32(av[l].z);
            As[row][c4 * 4 + 3] = f32_to_tf32(av[l].w);
        }
        #pragma unroll
        for (int l = 0; l < 2; ++l) {
            int idx = tid + l * 256;
            int row = idx >> 4;
            int c4  = idx & 15;
            Bs[row][c4 * 4 + 0] = f32_to_tf32(bv[l].x);
            Bs[row][c4 * 4 + 1] = f32_to_tf32(bv[l].y);
            Bs[row][c4 * 4 + 2] = f32_to_tf32(bv[l].z);
            Bs[row][c4 * 4 + 3] = f32_to_tf32(bv[l].w);
        }
        __syncthreads();

        // ---- compute: 4 k-steps of 8 ----
        #pragma unroll
        for (int k0 = 0; k0 < 32; k0 += 8) {
            uint32_t a[2][4];
            #pragma unroll
            for (int mt = 0; mt < 2; ++mt) {
                int mrow = wm * 32 + mt * 16 + t4;
                a[mt][0] = As[mrow][k0 + tc];
                a[mt][1] = As[mrow + 8][k0 + tc];
                a[mt][2] = As[mrow][k0 + tc + 4];
                a[mt][3] = As[mrow + 8][k0 + tc + 4];
            }
            #pragma unroll
            for (int nt = 0; nt < 4; ++nt) {
                int ncol = wn * 32 + nt * 8 + t4;
                uint32_t b0 = Bs[k0 + tc][ncol];
                uint32_t b1 = Bs[k0 + tc + 4][ncol];
                #pragma unroll
                for (int mt = 0; mt < 2; ++mt) {
                    asm volatile(
                        "mma.sync.aligned.m16n8k8.row.col.f32.tf32.tf32.f32 "
                        "{%0,%1,%2,%3}, {%4,%5,%6,%7}, {%8,%9}, {%0,%1,%2,%3};\n"
                        : "+f"(acc[mt][nt][0]), "+f"(acc[mt][nt][1]),
                          "+f"(acc[mt][nt][2]), "+f"(acc[mt][nt][3])
                        : "r"(a[mt][0]), "r"(a[mt][1]), "r"(a[mt][2]), "r"(a[mt][3]),
                          "r"(b0), "r"(b1));
                }
            }
        }
        __syncthreads();
    }

    // ---- epilogue: bias + relu, float2 stores ----
    #pragma unroll
    for (int nt = 0; nt < 4; ++nt) {
        int c = cb * 64 + wn * 32 + nt * 8 + 2 * tc;
        float2 bb = *(const float2*)(bias + c);
        #pragma unroll
        for (int mt = 0; mt < 2; ++mt) {
            int r = r0 + wm * 32 + mt * 16 + t4;
            if (r < M) {
                float2 o;
                o.x = fmaxf(acc[mt][nt][0] + bb.x, 0.f);
                o.y = fmaxf(acc[mt][nt][1] + bb.y, 0.f);
                *(float2*)(out + (size_t)r * DIM + c) = o;
                if (out2) *(float2*)(out2 + (size_t)r * DIM + c) = o;
            }
            if (r + 8 < M) {
                float2 o;
                o.x = fmaxf(acc[mt][nt][2] + bb.x, 0.f);
                o.y = fmaxf(acc[mt][nt][3] + bb.y, 0.f);
                *(float2*)(out + (size_t)(r + 8) * DIM + c) = o;
                if (out2) *(float2*)(out2 + (size_t)(r + 8) * DIM + c) = o;
            }
        }
    }
}

// ---------------------------------------------------------------------------
// Link predictor, batched: 32 pairs per 128-thread block.
// ---------------------------------------------------------------------------
#define PPB 32
__global__ __launch_bounds__(128) void pred_kernel(
    const int*   __restrict__ ps, const int* __restrict__ pd,
    const int*   __restrict__ ns, const int* __restrict__ nd,
    const float* __restrict__ pw1,    // [256, 128]
    const float* __restrict__ pb1,    // [128]
    const float* __restrict__ pw2,    // [128]
    const float* __restrict__ pb2,    // [1]
    float*       __restrict__ out)    // [10000] : pos then neg
{
    const float* h = g_h1;
    __shared__ float es[PPB][256];
    __shared__ int   sa[PPB], sb[PPB];
    __shared__ float s_part[4][PPB];

    int tid  = threadIdx.x;           // 0..127
    int lane = tid & 31;
    int wid  = tid >> 5;
    int pbase = blockIdx.x * PPB;

    if (tid < PPB) {
        int P = pbase + tid;
        int a = 0, b = 0;
        if (P < NPTOT) {
            if (P < NPAIR) { a = ps[P]; b = pd[P]; }
            else           { a = ns[P - NPAIR]; b = nd[P - NPAIR]; }
        }
        sa[tid] = a; sb[tid] = b;
    }
    __syncthreads();

    #pragma unroll 4
    for (int p = 0; p < PPB; ++p) {
        int a = sa[p], b = sb[p];
        es[p][tid]       = h[(size_t)a * DIM + tid]       * h[(size_t)b * DIM + tid];
        es[p][tid + 128] = h[(size_t)a * DIM + 128 + tid] * h[(size_t)b * DIM + 128 + tid];
    }
    __syncthreads();

    float acc[PPB];
    #pragma unroll
    for (int p = 0; p < PPB; ++p) acc[p] = 0.f;

    for (int j = 0; j < 256; j += 4) {
        float w0 = pw1[(j + 0) * 128 + tid];
        float w1 = pw1[(j + 1) * 128 + tid];
        float w2 = pw1[(j + 2) * 128 + tid];
        float w3 = pw1[(j + 3) * 128 + tid];
        #pragma unroll
        for (int p = 0; p < PPB; ++p) {
            float4 e4 = *(const float4*)&es[p][j];
            acc[p] += e4.x * w0 + e4.y * w1 + e4.z * w2 + e4.w * w3;
        }
    }

    float pb  = pb1[tid];
    float w2v = pw2[tid];
    #pragma unroll
    for (int p = 0; p < PPB; ++p) {
        float v = fmaxf(acc[p] + pb, 0.f) * w2v;
        #pragma unroll
        for (int o = 16; o; o >>= 1) v += __shfl_xor_sync(0xFFFFFFFFu, v, o);
        if (lane == 0) s_part[wid][p] = v;
    }
    __syncthreads();
    if (tid < PPB) {
        int P = pbase + tid;
        if (P < NPTOT)
            out[P] = s_part[0][tid] + s_part[1][tid] + s_part[2][tid] + s_part[3][tid]
                   + pb2[0];
    }
}

// ---------------------------------------------------------------------------
// Launch
// ---------------------------------------------------------------------------
extern "C" void kernel_launch(void* const* d_in, const int* in_sizes, int n_in,
                              void* d_out, int out_size)
{
    const float* x     = (const float*)d_in[0];
    const int*   src0  = (const int*)d_in[1];
    const int*   dst0  = (const int*)d_in[2];
    const int*   src1  = (const int*)d_in[3];
    const int*   dst1  = (const int*)d_in[4];
    const int*   psrc  = (const int*)d_in[5];
    const int*   pdst  = (const int*)d_in[6];
    const int*   nsrc  = (const int*)d_in[7];
    const int*   ndst  = (const int*)d_in[8];
    const float* W0    = (const float*)d_in[9];
    const float* loop0 = (const float*)d_in[10];
    const float* b0    = (const float*)d_in[11];
    const float* W1    = (const float*)d_in[12];
    const float* loop1 = (const float*)d_in[13];
    const float* b1    = (const float*)d_in[14];
    const float* pw1   = (const float*)d_in[15];
    const float* pb1   = (const float*)d_in[16];
    const float* pw2   = (const float*)d_in[17];
    const float* pb2   = (const float*)d_in[18];
    float*       out   = (float*)d_out;

    // CSR build for both layers (hierarchical parallel scan)
    zero_cnt_kernel<<<256, 256>>>();
    count_kernel<0><<<(NE0 + 255) / 256, 256>>>(dst0, NE0);
    count_kernel<1><<<(NE1 + 255) / 256, 256>>>(dst1, NE1);
    scan_a_kernel<0><<<NBLK0, 512>>>();
    scan_a_kernel<1><<<NBLK1, 512>>>();
    scan_b_kernel<0><<<NBLK0, 512>>>();
    scan_b_kernel<1><<<NBLK1, 512>>>();
    fill_kernel<0><<<(NE0 + 255) / 256, 256>>>(src0, dst0, NE0);
    fill_kernel<1><<<(NE1 + 255) / 256, 256>>>(src1, dst1, NE1);

    // layer 0: pull-aggregate x, fused tf32 transform -> h0
    gather_kernel<0><<<(N_DST0 + 1) / 2, 128>>>(x);
    {
        dim3 grid(NBASE, (N_DST0 + 127) / 128);
        layer_kernel<0><<<grid, 256>>>(x, W0, loop0, b0, nullptr, N_DST0);
    }

    // layer 1: pull-aggregate h0, fused transform -> h1 (+mirror to out)
    gather_kernel<1><<<(N_DST1 + 1) / 2, 128>>>(nullptr);
    {
        dim3 grid(NBASE, (N_DST1 + 127) / 128);
        layer_kernel<1><<<grid, 256>>>(nullptr, W1, loop1, b1,
                                       out + NPTOT, N_DST1);
    }

    // link prediction -> out[0:5000] (pos), out[5000:10000] (neg)
    pred_kernel<<<(NPTOT + PPB - 1) / PPB, 128>>>(psrc, pdst, nsrc, ndst,
                                                  pw1, pb1, pw2, pb2, out);
}

// round 8
// speedup vs baseline: 1.2376x; 1.0537x over previous
#include <cuda_runtime.h>
#include <cuda_fp16.h>
#include <stdint.h>

// Problem constants
#define N_SRC0 200000
#define N_DST0 50000
#define N_DST1 10000
#define NE0    800000
#define NE1    160000
#define DIM    256
#define NBASE  4
#define BD     64
#define NPAIR  5000
#define NPTOT  (2 * NPAIR)

#define SCAN_CHUNK 4096
#define NBLK0 ((N_DST0 + SCAN_CHUNK - 1) / SCAN_CHUNK)   // 13
#define NBLK1 ((N_DST1 + SCAN_CHUNK - 1) / SCAN_CHUNK)   // 3

// ---------------------------------------------------------------------------
// Scratch (__device__ globals; kernels reference them directly)
// ---------------------------------------------------------------------------
__device__ float  g_agg0[(size_t)N_DST0 * DIM];
__device__ float  g_agg1[(size_t)N_DST1 * DIM];
__device__ float  g_h0  [(size_t)N_DST0 * DIM];
__device__ float  g_h1  [(size_t)N_DST1 * DIM];
__device__ __align__(16) __half g_xh[(size_t)N_SRC0 * DIM];   // fp16 staged x

__device__ __align__(16) int g_cnt0[N_DST0];
__device__ __align__(16) int g_cnt1[N_DST1];
__device__ __align__(16) int g_rowptr0[N_DST0 + 1];
__device__ __align__(16) int g_rowptr1[N_DST1 + 1];
__device__ __align__(16) int g_cur0[N_DST0];
__device__ __align__(16) int g_cur1[N_DST1];
__device__ int g_esrc0[NE0];
__device__ int g_esrc1[NE1];
__device__ int g_part0[NBLK0];
__device__ int g_part1[NBLK1];

// ---------------------------------------------------------------------------
// Convert x (fp32) -> g_xh (fp16). 8 floats per thread, exact grid.
// ---------------------------------------------------------------------------
__global__ __launch_bounds__(256) void convert_kernel(const float* __restrict__ x) {
    size_t i = (size_t)blockIdx.x * 256 + threadIdx.x;   // 6.4M uint4 outputs
    const float4* x4 = (const float4*)x;
    float4 a = x4[2 * i];
    float4 b = x4[2 * i + 1];
    __half2 h0 = __floats2half2_rn(a.x, a.y);
    __half2 h1 = __floats2half2_rn(a.z, a.w);
    __half2 h2 = __floats2half2_rn(b.x, b.y);
    __half2 h3 = __floats2half2_rn(b.z, b.w);
    uint4 o;
    o.x = *(uint32_t*)&h0; o.y = *(uint32_t*)&h1;
    o.z = *(uint32_t*)&h2; o.w = *(uint32_t*)&h3;
    ((uint4*)g_xh)[i] = o;
}

// ---------------------------------------------------------------------------
// Zero the per-dst edge counters
// ---------------------------------------------------------------------------
__global__ void zero_cnt_kernel() {
    int stride = gridDim.x * blockDim.x;
    int i0 = blockIdx.x * blockDim.x + threadIdx.x;
    for (int i = i0; i < N_DST0; i += stride) g_cnt0[i] = 0;
    for (int i = i0; i < N_DST1; i += stride) g_cnt1[i] = 0;
}

// ---------------------------------------------------------------------------
// CSR build: count (both layers), hierarchical scan (2 phases), fill (both)
// ---------------------------------------------------------------------------
__global__ void count_kernel(const int* __restrict__ dst0,
                             const int* __restrict__ dst1) {
    int e = blockIdx.x * blockDim.x + threadIdx.x;
    if (e < NE0)             atomicAdd(&g_cnt0[dst0[e]], 1);
    else if (e < NE0 + NE1)  atomicAdd(&g_cnt1[dst1[e - NE0]], 1);
}

// Phase A: each block exclusive-scans a 4096-element chunk (local offsets)
// and records its chunk total. 512 threads x 8 elems. Both layers in one grid.
__global__ __launch_bounds__(512) void scan_a_kernel() {
    const int* cnt; int* rowptr; int* part; int n; int b;
    if ((int)blockIdx.x < NBLK0) {
        cnt = g_cnt0; rowptr = g_rowptr0; part = g_part0; n = N_DST0; b = blockIdx.x;
    } else {
        cnt = g_cnt1; rowptr = g_rowptr1; part = g_part1; n = N_DST1; b = blockIdx.x - NBLK0;
    }

    __shared__ int wsum[16];
    const int tid  = threadIdx.x;
    const int lane = tid & 31;
    const int wid  = tid >> 5;            // 0..15
    const int idx0 = b * SCAN_CHUNK + tid * 8;

    int v[8];
    if (idx0 + 8 <= n) {
        int4 a = *(const int4*)(cnt + idx0);
        int4 c = *(const int4*)(cnt + idx0 + 4);
        v[0]=a.x; v[1]=a.y; v[2]=a.z; v[3]=a.w;
        v[4]=c.x; v[5]=c.y; v[6]=c.z; v[7]=c.w;
    } else {
        #pragma unroll
        for (int j = 0; j < 8; ++j) v[j] = (idx0 + j < n) ? cnt[idx0 + j] : 0;
    }
    int incl[8]; int tot = 0;
    #pragma unroll
    for (int j = 0; j < 8; ++j) { tot += v[j]; incl[j] = tot; }

    int wincl = tot;
    #pragma unroll
    for (int o = 1; o < 32; o <<= 1) {
        int t = __shfl_up_sync(0xFFFFFFFFu, wincl, o);
        if (lane >= o) wincl += t;
    }
    if (lane == 31) wsum[wid] = wincl;
    __syncthreads();
    if (tid == 0) {
        int running = 0;
        #pragma unroll
        for (int w = 0; w < 16; ++w) { int t = wsum[w]; wsum[w] = running; running += t; }
        part[b] = running;
    }
    __syncthreads();

    int myexcl = wsum[wid] + (wincl - tot);
    if (idx0 + 8 <= n) {
        int4 r0 = make_int4(myexcl + incl[0]-v[0], myexcl + incl[1]-v[1],
                            myexcl + incl[2]-v[2], myexcl + incl[3]-v[3]);
        int4 r1 = make_int4(myexcl + incl[4]-v[4], myexcl + incl[5]-v[5],
                            myexcl + incl[6]-v[6], myexcl + incl[7]-v[7]);
        *(int4*)(rowptr + idx0)     = r0;
        *(int4*)(rowptr + idx0 + 4) = r1;
    } else {
        #pragma unroll
        for (int j = 0; j < 8; ++j)
            if (idx0 + j < n) rowptr[idx0 + j] = myexcl + incl[j] - v[j];
    }
}

// Phase B: each block adds the sum of preceding chunk totals, mirrors to cur.
__global__ __launch_bounds__(512) void scan_b_kernel() {
    int* rowptr; int* cur; const int* part; int n, nblk, b;
    if ((int)blockIdx.x < NBLK0) {
        rowptr = g_rowptr0; cur = g_cur0; part = g_part0;
        n = N_DST0; nblk = NBLK0; b = blockIdx.x;
    } else {
        rowptr = g_rowptr1; cur = g_cur1; part = g_part1;
        n = N_DST1; nblk = NBLK1; b = blockIdx.x - NBLK0;
    }
    int off = 0;
    for (int k = 0; k < b; ++k) off += part[k];

    const int tid  = threadIdx.x;
    const int idx0 = b * SCAN_CHUNK + tid * 8;
    if (idx0 + 8 <= n) {
        int4 a = *(const int4*)(rowptr + idx0);
        int4 c = *(const int4*)(rowptr + idx0 + 4);
        a.x += off; a.y += off; a.z += off; a.w += off;
        c.x += off; c.y += off; c.z += off; c.w += off;
        *(int4*)(rowptr + idx0)     = a;
        *(int4*)(rowptr + idx0 + 4) = c;
        *(int4*)(cur + idx0)        = a;
        *(int4*)(cur + idx0 + 4)    = c;
    } else {
        #pragma unroll
        for (int j = 0; j < 8; ++j) {
            int i = idx0 + j;
            if (i < n) { int e = rowptr[i] + off; rowptr[i] = e; cur[i] = e; }
        }
    }
    if (b == nblk - 1 && tid == 0) rowptr[n] = off + part[b];
}

__global__ void fill_kernel(const int* __restrict__ src0,
                            const int* __restrict__ dst0,
                            const int* __restrict__ src1,
                            const int* __restrict__ dst1) {
    int e = blockIdx.x * blockDim.x + threadIdx.x;
    if (e < NE0) {
        int p = atomicAdd(&g_cur0[dst0[e]], 1);
        g_esrc0[p] = src0[e];
    } else if (e < NE0 + NE1) {
        int e1 = e - NE0;
        int p = atomicAdd(&g_cur1[dst1[e1]], 1);
        g_esrc1[p] = src1[e1];
    }
}

// ---------------------------------------------------------------------------
// Layer-0 gather (fp16 source): agg0[d,:] = sum_e xh[esrc0[e], :]
// 32 threads per dst row (one uint4 = 8 halves each), 4 rows per block.
// fp32 accumulation.
// ---------------------------------------------------------------------------
__global__ __launch_bounds__(128) void gather0_kernel() {
    int d = blockIdx.x * 4 + (threadIdx.x >> 5);
    int lane = threadIdx.x & 31;
    if (d >= N_DST0) return;

    int beg = g_rowptr0[d], end = g_rowptr0[d + 1];
    float a0=0.f,a1=0.f,a2=0.f,a3=0.f,a4=0.f,a5=0.f,a6=0.f,a7=0.f;
    const uint4* xh = (const uint4*)g_xh;   // 32 uint4 per row

    int i = beg;
    for (; i + 1 < end; i += 2) {
        int s0 = g_esrc0[i], s1 = g_esrc0[i + 1];
        uint4 v0 = xh[(size_t)s0 * 32 + lane];
        uint4 v1 = xh[(size_t)s1 * 32 + lane];
        float2 f;
        f = __half22float2(*(__half2*)&v0.x); a0 += f.x; a1 += f.y;
        f = __half22float2(*(__half2*)&v0.y); a2 += f.x; a3 += f.y;
        f = __half22float2(*(__half2*)&v0.z); a4 += f.x; a5 += f.y;
        f = __half22float2(*(__half2*)&v0.w); a6 += f.x; a7 += f.y;
        f = __half22float2(*(__half2*)&v1.x); a0 += f.x; a1 += f.y;
        f = __half22float2(*(__half2*)&v1.y); a2 += f.x; a3 += f.y;
        f = __half22float2(*(__half2*)&v1.z); a4 += f.x; a5 += f.y;
        f = __half22float2(*(__half2*)&v1.w); a6 += f.x; a7 += f.y;
    }
    if (i < end) {
        int s0 = g_esrc0[i];
        uint4 v0 = xh[(size_t)s0 * 32 + lane];
        float2 f;
        f = __half22float2(*(__half2*)&v0.x); a0 += f.x; a1 += f.y;
        f = __half22float2(*(__half2*)&v0.y); a2 += f.x; a3 += f.y;
        f = __half22float2(*(__half2*)&v0.z); a4 += f.x; a5 += f.y;
        f = __half22float2(*(__half2*)&v0.w); a6 += f.x; a7 += f.y;
    }
    float* dst = g_agg0 + (size_t)d * DIM + lane * 8;
    *(float4*)(dst)     = make_float4(a0, a1, a2, a3);
    *(float4*)(dst + 4) = make_float4(a4, a5, a6, a7);
}

// ---------------------------------------------------------------------------
// Layer-1 gather (fp32 source h0): agg1[d,:] = sum_e h0[esrc1[e], :]
// 64 threads (float4 each) per row, 2 rows per 128-thread block.
// ---------------------------------------------------------------------------
__global__ __launch_bounds__(128) void gather1_kernel() {
    int d = blockIdx.x * 2 + (threadIdx.x >> 6);
    int lane = threadIdx.x & 63;
    if (d >= N_DST1) return;

    int beg = g_rowptr1[d], end = g_rowptr1[d + 1];
    float4 acc = make_float4(0.f, 0.f, 0.f, 0.f);
    const float4* f4 = (const float4*)g_h0;

    int i = beg;
    for (; i + 1 < end; i += 2) {
        int s0 = g_esrc1[i], s1 = g_esrc1[i + 1];
        float4 v0 = f4[(size_t)s0 * (DIM / 4) + lane];
        float4 v1 = f4[(size_t)s1 * (DIM / 4) + lane];
        acc.x += v0.x + v1.x; acc.y += v0.y + v1.y;
        acc.z += v0.z + v1.z; acc.w += v0.w + v1.w;
    }
    if (i < end) {
        int s0 = g_esrc1[i];
        float4 v0 = f4[(size_t)s0 * (DIM / 4) + lane];
        acc.x += v0.x; acc.y += v0.y; acc.z += v0.z; acc.w += v0.w;
    }
    ((float4*)g_agg1)[(size_t)d * (DIM / 4) + lane] = acc;
}

// ---------------------------------------------------------------------------
// tf32 tensor-core fused layer GEMM.
// Block tile 128x64, 256 threads (8 warps, 4x2 warp grid, 32x32 per warp).
// ---------------------------------------------------------------------------
__device__ __forceinline__ uint32_t f32_to_tf32(float f) {
    uint32_t u;
    asm("cvt.rna.tf32.f32 %0, %1;" : "=r"(u) : "f"(f));
    return u;
}

template <int LAYER>
__global__ __launch_bounds__(256) void layer_kernel(
    const float* __restrict__ xparam, // layer0: x; layer1 unused
    const float* __restrict__ W,      // [4,64,64]
    const float* __restrict__ loopw,  // [256,256]
    const float* __restrict__ bias,   // [256]
    float*       __restrict__ out2,   // optional mirror (may be null)
    int M)
{
    const float* agg = (LAYER == 0) ? g_agg0 : g_agg1;
    const float* xd  = (LAYER == 0) ? xparam : g_h0;
    float*       out = (LAYER == 0) ? g_h0   : g_h1;

    __shared__ uint32_t As[128][36];   // 128 rows x 32 k (pad 36)
    __shared__ uint32_t Bs[32][72];    // 32 k x 64 n (pad 72)

    const int cb  = blockIdx.x;        // output column block (0..3)
    const int r0  = blockIdx.y * 128;
    const int tid = threadIdx.x;
    const int lane = tid & 31;
    const int w   = tid >> 5;          // warp 0..7
    const int wm  = w & 3;             // warp row (4)
    const int wn  = w >> 2;            // warp col (2)
    const int t4  = lane >> 2;         // 0..7
    const int tc  = lane & 3;          // 0..3

    float acc[2][4][4];
    #pragma unroll
    for (int mt = 0; mt < 2; ++mt)
        #pragma unroll
        for (int nt = 0; nt < 4; ++nt)
            #pragma unroll
            for (int i = 0; i < 4; ++i) acc[mt][nt][i] = 0.f;

    for (int ch = 0; ch < 10; ++ch) {
        const float* amat = (ch < 8) ? xd : agg;
        const int akbase  = (ch < 8) ? ch * 32 : cb * 64 + (ch - 8) * 32;

        // ---- load A tile: 128x32, 4 float4 per thread ----
        float4 av[4];
        #pragma unroll
        for (int l = 0; l < 4; ++l) {
            int idx = tid + l * 256;        // 0..1023
            int row = idx >> 3;             // /8 (8 float4 per row)
            int c4  = idx & 7;
            av[l] = make_float4(0.f, 0.f, 0.f, 0.f);
            if (r0 + row < M)
                av[l] = *(const float4*)(amat + (size_t)(r0 + row) * DIM + akbase + c4 * 4);
        }
        // ---- load B tile: 32x64, 2 float4 per thread ----
        float4 bv[2];
        #pragma unroll
        for (int l = 0; l < 2; ++l) {
            int idx = tid + l * 256;        // 0..511
            int row = idx >> 4;             // /16 (16 float4 per row)
            int c4  = idx & 15;
            if (ch < 8)
                bv[l] = *(const float4*)(loopw + (size_t)(ch * 32 + row) * DIM + cb * 64 + c4 * 4);
            else
                bv[l] = *(const float4*)(W + (size_t)cb * BD * BD
                                           + (size_t)((ch - 8) * 32 + row) * BD + c4 * 4);
        }

        __syncthreads();   // previous chunk compute done

        #pragma unroll
        for (int l = 0; l < 4; ++l) {
            int idx = tid + l * 256;
            int row = idx >> 3;
            int c4  = idx & 7;
            As[row][c4 * 4 + 0] = f32_to_tf32(av[l].x);
            As[row][c4 * 4 + 1] = f32_to_tf32(av[l].y);
            As[row][c4 * 4 + 2] = f32_to_tf32(av[l].z);
            As[row][c4 * 4 + 3] = f32_to_tf32(av[l].w);
        }
        #pragma unroll
        for (int l = 0; l < 2; ++l) {
            int idx = tid + l * 256;
            int row = idx >> 4;
            int c4  = idx & 15;
            Bs[row][c4 * 4 + 0] = f32_to_tf32(bv[l].x);
            Bs[row][c4 * 4 + 1] = f32_to_tf32(bv[l].y);
            Bs[row][c4 * 4 + 2] = f32_to_tf32(bv[l].z);
            Bs[row][c4 * 4 + 3] = f32_to_tf32(bv[l].w);
        }
        __syncthreads();

        // ---- compute: 4 k-steps of 8 ----
        #pragma unroll
        for (int k0 = 0; k0 < 32; k0 += 8) {
            uint32_t a[2][4];
            #pragma unroll
            for (int mt = 0; mt < 2; ++mt) {
                int mrow = wm * 32 + mt * 16 + t4;
                a[mt][0] = As[mrow][k0 + tc];
                a[mt][1] = As[mrow + 8][k0 + tc];
                a[mt][2] = As[mrow][k0 + tc + 4];
                a[mt][3] = As[mrow + 8][k0 + tc + 4];
            }
            #pragma unroll
            for (int nt = 0; nt < 4; ++nt) {
                int ncol = wn * 32 + nt * 8 + t4;
                uint32_t b0 = Bs[k0 + tc][ncol];
                uint32_t b1 = Bs[k0 + tc + 4][ncol];
                #pragma unroll
                for (int mt = 0; mt < 2; ++mt) {
                    asm volatile(
                        "mma.sync.aligned.m16n8k8.row.col.f32.tf32.tf32.f32 "
                        "{%0,%1,%2,%3}, {%4,%5,%6,%7}, {%8,%9}, {%0,%1,%2,%3};\n"
                        : "+f"(acc[mt][nt][0]), "+f"(acc[mt][nt][1]),
                          "+f"(acc[mt][nt][2]), "+f"(acc[mt][nt][3])
                        : "r"(a[mt][0]), "r"(a[mt][1]), "r"(a[mt][2]), "r"(a[mt][3]),
                          "r"(b0), "r"(b1));
                }
            }
        }
        __syncthreads();
    }

    // ---- epilogue: bias + relu, float2 stores ----
    #pragma unroll
    for (int nt = 0; nt < 4; ++nt) {
        int c = cb * 64 + wn * 32 + nt * 8 + 2 * tc;
        float2 bb = *(const float2*)(bias + c);
        #pragma unroll
        for (int mt = 0; mt < 2; ++mt) {
            int r = r0 + wm * 32 + mt * 16 + t4;
            if (r < M) {
                float2 o;
                o.x = fmaxf(acc[mt][nt][0] + bb.x, 0.f);
                o.y = fmaxf(acc[mt][nt][1] + bb.y, 0.f);
                *(float2*)(out + (size_t)r * DIM + c) = o;
                if (out2) *(float2*)(out2 + (size_t)r * DIM + c) = o;
            }
            if (r + 8 < M) {
                float2 o;
                o.x = fmaxf(acc[mt][nt][2] + bb.x, 0.f);
                o.y = fmaxf(acc[mt][nt][3] + bb.y, 0.f);
                *(float2*)(out + (size_t)(r + 8) * DIM + c) = o;
                if (out2) *(float2*)(out2 + (size_t)(r + 8) * DIM + c) = o;
            }
        }
    }
}

// ---------------------------------------------------------------------------
// Link predictor, batched: 32 pairs per 128-thread block.
// ---------------------------------------------------------------------------
#define PPB 32
__global__ __launch_bounds__(128) void pred_kernel(
    const int*   __restrict__ ps, const int* __restrict__ pd,
    const int*   __restrict__ ns, const int* __restrict__ nd,
    const float* __restrict__ pw1,    // [256, 128]
    const float* __restrict__ pb1,    // [128]
    const float* __restrict__ pw2,    // [128]
    const float* __restrict__ pb2,    // [1]
    float*       __restrict__ out)    // [10000] : pos then neg
{
    const float* h = g_h1;
    __shared__ float es[PPB][256];
    __shared__ int   sa[PPB], sb[PPB];
    __shared__ float s_part[4][PPB];

    int tid  = threadIdx.x;           // 0..127
    int lane = tid & 31;
    int wid  = tid >> 5;
    int pbase = blockIdx.x * PPB;

    if (tid < PPB) {
        int P = pbase + tid;
        int a = 0, b = 0;
        if (P < NPTOT) {
            if (P < NPAIR) { a = ps[P]; b = pd[P]; }
            else           { a = ns[P - NPAIR]; b = nd[P - NPAIR]; }
        }
        sa[tid] = a; sb[tid] = b;
    }
    __syncthreads();

    #pragma unroll 4
    for (int p = 0; p < PPB; ++p) {
        int a = sa[p], b = sb[p];
        es[p][tid]       = h[(size_t)a * DIM + tid]       * h[(size_t)b * DIM + tid];
        es[p][tid + 128] = h[(size_t)a * DIM + 128 + tid] * h[(size_t)b * DIM + 128 + tid];
    }
    __syncthreads();

    float acc[PPB];
    #pragma unroll
    for (int p = 0; p < PPB; ++p) acc[p] = 0.f;

    for (int j = 0; j < 256; j += 4) {
        float w0 = pw1[(j + 0) * 128 + tid];
        float w1 = pw1[(j + 1) * 128 + tid];
        float w2 = pw1[(j + 2) * 128 + tid];
        float w3 = pw1[(j + 3) * 128 + tid];
        #pragma unroll
        for (int p = 0; p < PPB; ++p) {
            float4 e4 = *(const float4*)&es[p][j];
            acc[p] += e4.x * w0 + e4.y * w1 + e4.z * w2 + e4.w * w3;
        }
    }

    float pb  = pb1[tid];
    float w2v = pw2[tid];
    #pragma unroll
    for (int p = 0; p < PPB; ++p) {
        float v = fmaxf(acc[p] + pb, 0.f) * w2v;
        #pragma unroll
        for (int o = 16; o; o >>= 1) v += __shfl_xor_sync(0xFFFFFFFFu, v, o);
        if (lane == 0) s_part[wid][p] = v;
    }
    __syncthreads();
    if (tid < PPB) {
        int P = pbase + tid;
        if (P < NPTOT)
            out[P] = s_part[0][tid] + s_part[1][tid] + s_part[2][tid] + s_part[3][tid]
                   + pb2[0];
    }
}

// ---------------------------------------------------------------------------
// Launch
// ---------------------------------------------------------------------------
extern "C" void kernel_launch(void* const* d_in, const int* in_sizes, int n_in,
                              void* d_out, int out_size)
{
    const float* x     = (const float*)d_in[0];
    const int*   src0  = (const int*)d_in[1];
    const int*   dst0  = (const int*)d_in[2];
    const int*   src1  = (const int*)d_in[3];
    const int*   dst1  = (const int*)d_in[4];
    const int*   psrc  = (const int*)d_in[5];
    const int*   pdst  = (const int*)d_in[6];
    const int*   nsrc  = (const int*)d_in[7];
    const int*   ndst  = (const int*)d_in[8];
    const float* W0    = (const float*)d_in[9];
    const float* loop0 = (const float*)d_in[10];
    const float* b0    = (const float*)d_in[11];
    const float* W1    = (const float*)d_in[12];
    const float* loop1 = (const float*)d_in[13];
    const float* b1    = (const float*)d_in[14];
    const float* pw1   = (const float*)d_in[15];
    const float* pb1   = (const float*)d_in[16];
    const float* pw2   = (const float*)d_in[17];
    const float* pb2   = (const float*)d_in[18];
    float*       out   = (float*)d_out;

    // Stage x in fp16 (independent of CSR build)
    convert_kernel<<<(N_SRC0 * DIM / 8) / 256, 256>>>(x);

    // CSR build for both layers (merged launches, hierarchical scan)
    zero_cnt_kernel<<<256, 256>>>();
    count_kernel<<<(NE0 + NE1 + 255) / 256, 256>>>(dst0, dst1);
    scan_a_kernel<<<NBLK0 + NBLK1, 512>>>();
    scan_b_kernel<<<NBLK0 + NBLK1, 512>>>();
    fill_kernel<<<(NE0 + NE1 + 255) / 256, 256>>>(src0, dst0, src1, dst1);

    // layer 0: pull-aggregate xh (fp16), fused tf32 transform -> h0
    gather0_kernel<<<(N_DST0 + 3) / 4, 128>>>();
    {
        dim3 grid(NBASE, (N_DST0 + 127) / 128);
        layer_kernel<0><<<grid, 256>>>(x, W0, loop0, b0, nullptr, N_DST0);
    }

    // layer 1: pull-aggregate h0 (fp32), fused transform -> h1 (+mirror to out)
    gather1_kernel<<<(N_DST1 + 1) / 2, 128>>>();
    {
        dim3 grid(NBASE, (N_DST1 + 127) / 128);
        layer_kernel<1><<<grid, 256>>>(nullptr, W1, loop1, b1,
                                       out + NPTOT, N_DST1);
    }

    // link prediction -> out[0:5000] (pos), out[5000:10000] (neg)
    pred_kernel<<<(NPTOT + PPB - 1) / PPB, 128>>>(psrc, pdst, nsrc, ndst,
                                                  pw1, pb1, pw2, pb2, out);
}

// round 9
// speedup vs baseline: 1.3944x; 1.1267x over previous
#include <cuda_runtime.h>
#include <cuda_fp16.h>
#include <stdint.h>

// Problem constants
#define N_SRC0 200000
#define N_DST0 50000
#define N_DST1 10000
#define NE0    800000
#define NE1    160000
#define DIM    256
#define NBASE  4
#define BD     64
#define NPAIR  5000
#define NPTOT  (2 * NPAIR)

#define SCAN_CHUNK 4096
#define NBLK0 ((N_DST0 + SCAN_CHUNK - 1) / SCAN_CHUNK)   // 13
#define NBLK1 ((N_DST1 + SCAN_CHUNK - 1) / SCAN_CHUNK)   // 3

// ---------------------------------------------------------------------------
// Scratch (__device__ globals; kernels reference them directly)
// ---------------------------------------------------------------------------
__device__ float  g_agg0[(size_t)N_DST0 * DIM];
__device__ float  g_agg1[(size_t)N_DST1 * DIM];
__device__ float  g_h0  [(size_t)N_DST0 * DIM];
__device__ float  g_h1  [(size_t)N_DST1 * DIM];
__device__ __align__(16) __half g_xh[(size_t)N_SRC0 * DIM];   // fp16 staged x

__device__ __align__(16) int g_cnt0[N_DST0];
__device__ __align__(16) int g_cnt1[N_DST1];
__device__ __align__(16) int g_rowptr0[N_DST0 + 1];
__device__ __align__(16) int g_rowptr1[N_DST1 + 1];
__device__ __align__(16) int g_cur0[N_DST0];
__device__ __align__(16) int g_cur1[N_DST1];
__device__ int g_esrc0[NE0];
__device__ int g_esrc1[NE1];
__device__ int g_part0[NBLK0];
__device__ int g_part1[NBLK1];

// ---------------------------------------------------------------------------
// Convert x (fp32) -> g_xh (fp16). 8 floats per thread, exact grid.
// ---------------------------------------------------------------------------
__global__ __launch_bounds__(256) void convert_kernel(const float* __restrict__ x) {
    size_t i = (size_t)blockIdx.x * 256 + threadIdx.x;
    const float4* x4 = (const float4*)x;
    float4 a = x4[2 * i];
    float4 b = x4[2 * i + 1];
    __half2 h0 = __floats2half2_rn(a.x, a.y);
    __half2 h1 = __floats2half2_rn(a.z, a.w);
    __half2 h2 = __floats2half2_rn(b.x, b.y);
    __half2 h3 = __floats2half2_rn(b.z, b.w);
    uint4 o;
    o.x = *(uint32_t*)&h0; o.y = *(uint32_t*)&h1;
    o.z = *(uint32_t*)&h2; o.w = *(uint32_t*)&h3;
    ((uint4*)g_xh)[i] = o;
}

// ---------------------------------------------------------------------------
// Zero the per-dst edge counters
// ---------------------------------------------------------------------------
__global__ void zero_cnt_kernel() {
    int stride = gridDim.x * blockDim.x;
    int i0 = blockIdx.x * blockDim.x + threadIdx.x;
    for (int i = i0; i < N_DST0; i += stride) g_cnt0[i] = 0;
    for (int i = i0; i < N_DST1; i += stride) g_cnt1[i] = 0;
}

// ---------------------------------------------------------------------------
// CSR build: count (both layers), hierarchical scan (2 phases), fill (both)
// ---------------------------------------------------------------------------
__global__ void count_kernel(const int* __restrict__ dst0,
                             const int* __restrict__ dst1) {
    int e = blockIdx.x * blockDim.x + threadIdx.x;
    if (e < NE0)             atomicAdd(&g_cnt0[dst0[e]], 1);
    else if (e < NE0 + NE1)  atomicAdd(&g_cnt1[dst1[e - NE0]], 1);
}

__global__ __launch_bounds__(512) void scan_a_kernel() {
    const int* cnt; int* rowptr; int* part; int n; int b;
    if ((int)blockIdx.x < NBLK0) {
        cnt = g_cnt0; rowptr = g_rowptr0; part = g_part0; n = N_DST0; b = blockIdx.x;
    } else {
        cnt = g_cnt1; rowptr = g_rowptr1; part = g_part1; n = N_DST1; b = blockIdx.x - NBLK0;
    }

    __shared__ int wsum[16];
    const int tid  = threadIdx.x;
    const int lane = tid & 31;
    const int wid  = tid >> 5;
    const int idx0 = b * SCAN_CHUNK + tid * 8;

    int v[8];
    if (idx0 + 8 <= n) {
        int4 a = *(const int4*)(cnt + idx0);
        int4 c = *(const int4*)(cnt + idx0 + 4);
        v[0]=a.x; v[1]=a.y; v[2]=a.z; v[3]=a.w;
        v[4]=c.x; v[5]=c.y; v[6]=c.z; v[7]=c.w;
    } else {
        #pragma unroll
        for (int j = 0; j < 8; ++j) v[j] = (idx0 + j < n) ? cnt[idx0 + j] : 0;
    }
    int incl[8]; int tot = 0;
    #pragma unroll
    for (int j = 0; j < 8; ++j) { tot += v[j]; incl[j] = tot; }

    int wincl = tot;
    #pragma unroll
    for (int o = 1; o < 32; o <<= 1) {
        int t = __shfl_up_sync(0xFFFFFFFFu, wincl, o);
        if (lane >= o) wincl += t;
    }
    if (lane == 31) wsum[wid] = wincl;
    __syncthreads();
    if (tid == 0) {
        int running = 0;
        #pragma unroll
        for (int w = 0; w < 16; ++w) { int t = wsum[w]; wsum[w] = running; running += t; }
        part[b] = running;
    }
    __syncthreads();

    int myexcl = wsum[wid] + (wincl - tot);
    if (idx0 + 8 <= n) {
        int4 r0 = make_int4(myexcl + incl[0]-v[0], myexcl + incl[1]-v[1],
                            myexcl + incl[2]-v[2], myexcl + incl[3]-v[3]);
        int4 r1 = make_int4(myexcl + incl[4]-v[4], myexcl + incl[5]-v[5],
                            myexcl + incl[6]-v[6], myexcl + incl[7]-v[7]);
        *(int4*)(rowptr + idx0)     = r0;
        *(int4*)(rowptr + idx0 + 4) = r1;
    } else {
        #pragma unroll
        for (int j = 0; j < 8; ++j)
            if (idx0 + j < n) rowptr[idx0 + j] = myexcl + incl[j] - v[j];
    }
}

__global__ __launch_bounds__(512) void scan_b_kernel() {
    int* rowptr; int* cur; const int* part; int n, nblk, b;
    if ((int)blockIdx.x < NBLK0) {
        rowptr = g_rowptr0; cur = g_cur0; part = g_part0;
        n = N_DST0; nblk = NBLK0; b = blockIdx.x;
    } else {
        rowptr = g_rowptr1; cur = g_cur1; part = g_part1;
        n = N_DST1; nblk = NBLK1; b = blockIdx.x - NBLK0;
    }
    int off = 0;
    for (int k = 0; k < b; ++k) off += part[k];

    const int tid  = threadIdx.x;
    const int idx0 = b * SCAN_CHUNK + tid * 8;
    if (idx0 + 8 <= n) {
        int4 a = *(const int4*)(rowptr + idx0);
        int4 c = *(const int4*)(rowptr + idx0 + 4);
        a.x += off; a.y += off; a.z += off; a.w += off;
        c.x += off; c.y += off; c.z += off; c.w += off;
        *(int4*)(rowptr + idx0)     = a;
        *(int4*)(rowptr + idx0 + 4) = c;
        *(int4*)(cur + idx0)        = a;
        *(int4*)(cur + idx0 + 4)    = c;
    } else {
        #pragma unroll
        for (int j = 0; j < 8; ++j) {
            int i = idx0 + j;
            if (i < n) { int e = rowptr[i] + off; rowptr[i] = e; cur[i] = e; }
        }
    }
    if (b == nblk - 1 && tid == 0) rowptr[n] = off + part[b];
}

__global__ void fill_kernel(const int* __restrict__ src0,
                            const int* __restrict__ dst0,
                            const int* __restrict__ src1,
                            const int* __restrict__ dst1) {
    int e = blockIdx.x * blockDim.x + threadIdx.x;
    if (e < NE0) {
        int p = atomicAdd(&g_cur0[dst0[e]], 1);
        g_esrc0[p] = src0[e];
    } else if (e < NE0 + NE1) {
        int e1 = e - NE0;
        int p = atomicAdd(&g_cur1[dst1[e1]], 1);
        g_esrc1[p] = src1[e1];
    }
}

// ---------------------------------------------------------------------------
// Layer-0 gather (fp16 source): agg0[d,:] = sum_e xh[esrc0[e], :]
// 32 threads per dst row (one uint4 = 8 halves each), 4 rows per block.
// ---------------------------------------------------------------------------
__global__ __launch_bounds__(128) void gather0_kernel() {
    int d = blockIdx.x * 4 + (threadIdx.x >> 5);
    int lane = threadIdx.x & 31;
    if (d >= N_DST0) return;

    int beg = g_rowptr0[d], end = g_rowptr0[d + 1];
    float a0=0.f,a1=0.f,a2=0.f,a3=0.f,a4=0.f,a5=0.f,a6=0.f,a7=0.f;
    const uint4* xh = (const uint4*)g_xh;

    int i = beg;
    for (; i + 1 < end; i += 2) {
        int s0 = g_esrc0[i], s1 = g_esrc0[i + 1];
        uint4 v0 = xh[(size_t)s0 * 32 + lane];
        uint4 v1 = xh[(size_t)s1 * 32 + lane];
        float2 f;
        f = __half22float2(*(__half2*)&v0.x); a0 += f.x; a1 += f.y;
        f = __half22float2(*(__half2*)&v0.y); a2 += f.x; a3 += f.y;
        f = __half22float2(*(__half2*)&v0.z); a4 += f.x; a5 += f.y;
        f = __half22float2(*(__half2*)&v0.w); a6 += f.x; a7 += f.y;
        f = __half22float2(*(__half2*)&v1.x); a0 += f.x; a1 += f.y;
        f = __half22float2(*(__half2*)&v1.y); a2 += f.x; a3 += f.y;
        f = __half22float2(*(__half2*)&v1.z); a4 += f.x; a5 += f.y;
        f = __half22float2(*(__half2*)&v1.w); a6 += f.x; a7 += f.y;
    }
    if (i < end) {
        int s0 = g_esrc0[i];
        uint4 v0 = xh[(size_t)s0 * 32 + lane];
        float2 f;
        f = __half22float2(*(__half2*)&v0.x); a0 += f.x; a1 += f.y;
        f = __half22float2(*(__half2*)&v0.y); a2 += f.x; a3 += f.y;
        f = __half22float2(*(__half2*)&v0.z); a4 += f.x; a5 += f.y;
        f = __half22float2(*(__half2*)&v0.w); a6 += f.x; a7 += f.y;
    }
    float* dst = g_agg0 + (size_t)d * DIM + lane * 8;
    *(float4*)(dst)     = make_float4(a0, a1, a2, a3);
    *(float4*)(dst + 4) = make_float4(a4, a5, a6, a7);
}

// ---------------------------------------------------------------------------
// Layer-1 gather (fp32 source h0)
// ---------------------------------------------------------------------------
__global__ __launch_bounds__(128) void gather1_kernel() {
    int d = blockIdx.x * 2 + (threadIdx.x >> 6);
    int lane = threadIdx.x & 63;
    if (d >= N_DST1) return;

    int beg = g_rowptr1[d], end = g_rowptr1[d + 1];
    float4 acc = make_float4(0.f, 0.f, 0.f, 0.f);
    const float4* f4 = (const float4*)g_h0;

    int i = beg;
    for (; i + 1 < end; i += 2) {
        int s0 = g_esrc1[i], s1 = g_esrc1[i + 1];
        float4 v0 = f4[(size_t)s0 * (DIM / 4) + lane];
        float4 v1 = f4[(size_t)s1 * (DIM / 4) + lane];
        acc.x += v0.x + v1.x; acc.y += v0.y + v1.y;
        acc.z += v0.z + v1.z; acc.w += v0.w + v1.w;
    }
    if (i < end) {
        int s0 = g_esrc1[i];
        float4 v0 = f4[(size_t)s0 * (DIM / 4) + lane];
        acc.x += v0.x; acc.y += v0.y; acc.z += v0.z; acc.w += v0.w;
    }
    ((float4*)g_agg1)[(size_t)d * (DIM / 4) + lane] = acc;
}

// ---------------------------------------------------------------------------
// fp16 tensor-core fused layer GEMM (fp32 accumulate).
//   out[r,c] = relu( xd[r,:] @ loopw[:,c] (K=256)
//                  + agg[r, cb*64:+64] @ W[cb][:, c%64] (K=64) + bias[c] )
// Block tile 128x64, 256 threads, 8 warps (4x2), 32x32 per warp.
// mma.m16n8k16: 2 k-steps per 32-wide chunk.
// Layer0 xd chunks come straight from fp16 g_xh (no conversion).
// ---------------------------------------------------------------------------
__device__ __forceinline__ __half2 f2h2(float a, float b) {
    return __floats2half2_rn(a, b);
}

template <int LAYER>
__global__ __launch_bounds__(256) void layer_kernel(
    const float* __restrict__ W,      // [4,64,64]
    const float* __restrict__ loopw,  // [256,256]
    const float* __restrict__ bias,   // [256]
    float*       __restrict__ out2,   // optional mirror (may be null)
    int M)
{
    const float* agg = (LAYER == 0) ? g_agg0 : g_agg1;
    const float* xd  = (LAYER == 0) ? nullptr : g_h0;   // layer0 uses g_xh
    float*       out = (LAYER == 0) ? g_h0   : g_h1;

    __shared__ __half As[128][40];   // 128 rows x 32 k  (pad -> 40)
    __shared__ __half Bs[32][72];    // 32 k x 64 n      (pad -> 72)

    const int cb  = blockIdx.x;        // output column block (0..3)
    const int r0  = blockIdx.y * 128;
    const int tid = threadIdx.x;
    const int lane = tid & 31;
    const int w   = tid >> 5;
    const int wm  = w & 3;             // warp row (4)
    const int wn  = w >> 2;            // warp col (2)
    const int t4  = lane >> 2;         // 0..7 (group)
    const int tc  = lane & 3;          // 0..3

    float acc[2][4][4];
    #pragma unroll
    for (int mt = 0; mt < 2; ++mt)
        #pragma unroll
        for (int nt = 0; nt < 4; ++nt)
            #pragma unroll
            for (int i = 0; i < 4; ++i) acc[mt][nt][i] = 0.f;

    for (int ch = 0; ch < 10; ++ch) {
        const int akbase = (ch < 8) ? ch * 32 : cb * 64 + (ch - 8) * 32;

        // ---- stage A tile into registers: 2 uint4 (8 halves each) / thread ----
        uint4 areg[2];
        #pragma unroll
        for (int l = 0; l < 2; ++l) {
            int idx = tid + l * 256;        // 0..511
            int row = idx >> 2;             // 0..127
            int q   = idx & 3;              // 8-half column group
            bool ok = (r0 + row < M);
            if (LAYER == 0 && ch < 8) {
                areg[l] = ok ? *(const uint4*)(g_xh + (size_t)(r0 + row) * DIM + akbase + q * 8)
                             : make_uint4(0u, 0u, 0u, 0u);
            } else {
                const float* amat = (ch < 8) ? xd : agg;
                float4 fa = make_float4(0.f,0.f,0.f,0.f), fb = fa;
                if (ok) {
                    const float* p = amat + (size_t)(r0 + row) * DIM + akbase + q * 8;
                    fa = *(const float4*)p;
                    fb = *(const float4*)(p + 4);
                }
                __half2 h0 = f2h2(fa.x, fa.y), h1 = f2h2(fa.z, fa.w);
                __half2 h2 = f2h2(fb.x, fb.y), h3 = f2h2(fb.z, fb.w);
                areg[l].x = *(uint32_t*)&h0; areg[l].y = *(uint32_t*)&h1;
                areg[l].z = *(uint32_t*)&h2; areg[l].w = *(uint32_t*)&h3;
            }
        }
        // ---- stage B tile: 8 halves / thread ----
        // thread: k = tid>>3 (0..31), q = tid&7 -> n = q*8
        uint4 breg;
        {
            int k = tid >> 3;
            int q = tid & 7;
            const float* p = (ch < 8)
                ? loopw + (size_t)(ch * 32 + k) * DIM + cb * 64 + q * 8
                : W + (size_t)cb * BD * BD + (size_t)((ch - 8) * 32 + k) * BD + q * 8;
            float4 fa = *(const float4*)p;
            float4 fb = *(const float4*)(p + 4);
            __half2 h0 = f2h2(fa.x, fa.y), h1 = f2h2(fa.z, fa.w);
            __half2 h2 = f2h2(fb.x, fb.y), h3 = f2h2(fb.z, fb.w);
            breg.x = *(uint32_t*)&h0; breg.y = *(uint32_t*)&h1;
            breg.z = *(uint32_t*)&h2; breg.w = *(uint32_t*)&h3;
        }

        __syncthreads();   // previous chunk compute done

        #pragma unroll
        for (int l = 0; l < 2; ++l) {
            int idx = tid + l * 256;
            int row = idx >> 2;
            int q   = idx & 3;
            *(uint4*)&As[row][q * 8] = areg[l];
        }
        {
            int k = tid >> 3;
            int q = tid & 7;
            *(uint4*)&Bs[k][q * 8] = breg;
        }
        __syncthreads();

        // ---- compute: 2 k-steps of 16 ----
        #pragma unroll
        for (int ks = 0; ks < 2; ++ks) {
            const int kb = ks * 16;
            uint32_t a[2][4];
            #pragma unroll
            for (int mt = 0; mt < 2; ++mt) {
                int mrow = wm * 32 + mt * 16 + t4;
                a[mt][0] = *(const uint32_t*)&As[mrow][kb + 2 * tc];
                a[mt][1] = *(const uint32_t*)&As[mrow + 8][kb + 2 * tc];
                a[mt][2] = *(const uint32_t*)&As[mrow][kb + 2 * tc + 8];
                a[mt][3] = *(const uint32_t*)&As[mrow + 8][kb + 2 * tc + 8];
            }
            #pragma unroll
            for (int nt = 0; nt < 4; ++nt) {
                int ncol = wn * 32 + nt * 8 + t4;
                uint32_t b0 = (uint32_t)*(const uint16_t*)&Bs[kb + 2 * tc][ncol]
                            | ((uint32_t)*(const uint16_t*)&Bs[kb + 2 * tc + 1][ncol] << 16);
                uint32_t b1 = (uint32_t)*(const uint16_t*)&Bs[kb + 2 * tc + 8][ncol]
                            | ((uint32_t)*(const uint16_t*)&Bs[kb + 2 * tc + 9][ncol] << 16);
                #pragma unroll
                for (int mt = 0; mt < 2; ++mt) {
                    asm volatile(
                        "mma.sync.aligned.m16n8k16.row.col.f32.f16.f16.f32 "
                        "{%0,%1,%2,%3}, {%4,%5,%6,%7}, {%8,%9}, {%0,%1,%2,%3};\n"
                        : "+f"(acc[mt][nt][0]), "+f"(acc[mt][nt][1]),
                          "+f"(acc[mt][nt][2]), "+f"(acc[mt][nt][3])
                        : "r"(a[mt][0]), "r"(a[mt][1]), "r"(a[mt][2]), "r"(a[mt][3]),
                          "r"(b0), "r"(b1));
                }
            }
        }
        __syncthreads();
    }

    // ---- epilogue: bias + relu, float2 stores ----
    #pragma unroll
    for (int nt = 0; nt < 4; ++nt) {
        int c = cb * 64 + wn * 32 + nt * 8 + 2 * tc;
        float2 bb = *(const float2*)(bias + c);
        #pragma unroll
        for (int mt = 0; mt < 2; ++mt) {
            int r = r0 + wm * 32 + mt * 16 + t4;
            if (r < M) {
                float2 o;
                o.x = fmaxf(acc[mt][nt][0] + bb.x, 0.f);
                o.y = fmaxf(acc[mt][nt][1] + bb.y, 0.f);
                *(float2*)(out + (size_t)r * DIM + c) = o;
                if (out2) *(float2*)(out2 + (size_t)r * DIM + c) = o;
            }
            if (r + 8 < M) {
                float2 o;
                o.x = fmaxf(acc[mt][nt][2] + bb.x, 0.f);
                o.y = fmaxf(acc[mt][nt][3] + bb.y, 0.f);
                *(float2*)(out + (size_t)(r + 8) * DIM + c) = o;
                if (out2) *(float2*)(out2 + (size_t)(r + 8) * DIM + c) = o;
            }
        }
    }
}

// ---------------------------------------------------------------------------
// Link predictor, batched: 32 pairs per 128-thread block.
// ---------------------------------------------------------------------------
#define PPB 32
__global__ __launch_bounds__(128) void pred_kernel(
    const int*   __restrict__ ps, const int* __restrict__ pd,
    const int*   __restrict__ ns, const int* __restrict__ nd,
    const float* __restrict__ pw1,    // [256, 128]
    const float* __restrict__ pb1,    // [128]
    const float* __restrict__ pw2,    // [128]
    const float* __restrict__ pb2,    // [1]
    float*       __restrict__ out)    // [10000] : pos then neg
{
    const float* h = g_h1;
    __shared__ float es[PPB][256];
    __shared__ int   sa[PPB], sb[PPB];
    __shared__ float s_part[4][PPB];

    int tid  = threadIdx.x;
    int lane = tid & 31;
    int wid  = tid >> 5;
    int pbase = blockIdx.x * PPB;

    if (tid < PPB) {
        int P = pbase + tid;
        int a = 0, b = 0;
        if (P < NPTOT) {
            if (P < NPAIR) { a = ps[P]; b = pd[P]; }
            else           { a = ns[P - NPAIR]; b = nd[P - NPAIR]; }
        }
        sa[tid] = a; sb[tid] = b;
    }
    __syncthreads();

    #pragma unroll 4
    for (int p = 0; p < PPB; ++p) {
        int a = sa[p], b = sb[p];
        es[p][tid]       = h[(size_t)a * DIM + tid]       * h[(size_t)b * DIM + tid];
        es[p][tid + 128] = h[(size_t)a * DIM + 128 + tid] * h[(size_t)b * DIM + 128 + tid];
    }
    __syncthreads();

    float acc[PPB];
    #pragma unroll
    for (int p = 0; p < PPB; ++p) acc[p] = 0.f;

    for (int j = 0; j < 256; j += 4) {
        float w0 = pw1[(j + 0) * 128 + tid];
        float w1 = pw1[(j + 1) * 128 + tid];
        float w2 = pw1[(j + 2) * 128 + tid];
        float w3 = pw1[(j + 3) * 128 + tid];
        #pragma unroll
        for (int p = 0; p < PPB; ++p) {
            float4 e4 = *(const float4*)&es[p][j];
            acc[p] += e4.x * w0 + e4.y * w1 + e4.z * w2 + e4.w * w3;
        }
    }

    float pb  = pb1[tid];
    float w2v = pw2[tid];
    #pragma unroll
    for (int p = 0; p < PPB; ++p) {
        float v = fmaxf(acc[p] + pb, 0.f) * w2v;
        #pragma unroll
        for (int o = 16; o; o >>= 1) v += __shfl_xor_sync(0xFFFFFFFFu, v, o);
        if (lane == 0) s_part[wid][p] = v;
    }
    __syncthreads();
    if (tid < PPB) {
        int P = pbase + tid;
        if (P < NPTOT)
            out[P] = s_part[0][tid] + s_part[1][tid] + s_part[2][tid] + s_part[3][tid]
                   + pb2[0];
    }
}

// ---------------------------------------------------------------------------
// Launch
// ---------------------------------------------------------------------------
extern "C" void kernel_launch(void* const* d_in, const int* in_sizes, int n_in,
                              void* d_out, int out_size)
{
    const float* x     = (const float*)d_in[0];
    const int*   src0  = (const int*)d_in[1];
    const int*   dst0  = (const int*)d_in[2];
    const int*   src1  = (const int*)d_in[3];
    const int*   dst1  = (const int*)d_in[4];
    const int*   psrc  = (const int*)d_in[5];
    const int*   pdst  = (const int*)d_in[6];
    const int*   nsrc  = (const int*)d_in[7];
    const int*   ndst  = (const int*)d_in[8];
    const float* W0    = (const float*)d_in[9];
    const float* loop0 = (const float*)d_in[10];
    const float* b0    = (const float*)d_in[11];
    const float* W1    = (const float*)d_in[12];
    const float* loop1 = (const float*)d_in[13];
    const float* b1    = (const float*)d_in[14];
    const float* pw1   = (const float*)d_in[15];
    const float* pb1   = (const float*)d_in[16];
    const float* pw2   = (const float*)d_in[17];
    const float* pb2   = (const float*)d_in[18];
    float*       out   = (float*)d_out;

    // Stage x in fp16 (feeds both gather0 and layer0's A operand)
    convert_kernel<<<(N_SRC0 * DIM / 8) / 256, 256>>>(x);

    // CSR build for both layers (merged launches, hierarchical scan)
    zero_cnt_kernel<<<256, 256>>>();
    count_kernel<<<(NE0 + NE1 + 255) / 256, 256>>>(dst0, dst1);
    scan_a_kernel<<<NBLK0 + NBLK1, 512>>>();
    scan_b_kernel<<<NBLK0 + NBLK1, 512>>>();
    fill_kernel<<<(NE0 + NE1 + 255) / 256, 256>>>(src0, dst0, src1, dst1);

    // layer 0: pull-aggregate xh (fp16), fused fp16-mma transform -> h0
    gather0_kernel<<<(N_DST0 + 3) / 4, 128>>>();
    {
        dim3 grid(NBASE, (N_DST0 + 127) / 128);
        layer_kernel<0><<<grid, 256>>>(W0, loop0, b0, nullptr, N_DST0);
    }

    // layer 1: pull-aggregate h0 (fp32), fused transform -> h1 (+mirror to out)
    gather1_kernel<<<(N_DST1 + 1) / 2, 128>>>();
    {
        dim3 grid(NBASE, (N_DST1 + 127) / 128);
        layer_kernel<1><<<grid, 256>>>(W1, loop1, b1, out + NPTOT, N_DST1);
    }

    // link prediction -> out[0:5000] (pos), out[5000:10000] (neg)
    pred_kernel<<<(NPTOT + PPB - 1) / PPB, 128>>>(psrc, pdst, nsrc, ndst,
                                                  pw1, pb1, pw2, pb2, out);
}

// round 10
// speedup vs baseline: 1.5098x; 1.0827x over previous
#include <cuda_runtime.h>
#include <cuda_fp16.h>
#include <stdint.h>

// Problem constants
#define N_SRC0 200000
#define N_DST0 50000
#define N_DST1 10000
#define NE0    800000
#define NE1    160000
#define DIM    256
#define NBASE  4
#define BD     64
#define NPAIR  5000
#define NPTOT  (2 * NPAIR)

#define SCAN_CHUNK 4096
#define NBLK0 ((N_DST0 + SCAN_CHUNK - 1) / SCAN_CHUNK)   // 13
#define NBLK1 ((N_DST1 + SCAN_CHUNK - 1) / SCAN_CHUNK)   // 3

#define NCNT_BLK ((NE0 + NE1 + 255) / 256)               // 3750
#define NCVT_BLK ((N_SRC0 * (DIM / 8)) / 256)            // 25000

// ---------------------------------------------------------------------------
// Scratch (__device__ globals; kernels reference them directly)
// ---------------------------------------------------------------------------
__device__ float  g_agg0[(size_t)N_DST0 * DIM];
__device__ float  g_agg1[(size_t)N_DST1 * DIM];
__device__ __align__(16) __half g_h0h[(size_t)N_DST0 * DIM];  // fp16 h0
__device__ float  g_h1  [(size_t)N_DST1 * DIM];
__device__ __align__(16) __half g_xh[(size_t)N_SRC0 * DIM];   // fp16 staged x

__device__ __align__(16) int g_cnt0[N_DST0];
__device__ __align__(16) int g_cnt1[N_DST1];
__device__ __align__(16) int g_rowptr0[N_DST0 + 1];
__device__ __align__(16) int g_rowptr1[N_DST1 + 1];
__device__ __align__(16) int g_cur0[N_DST0];
__device__ __align__(16) int g_cur1[N_DST1];
__device__ int g_esrc0[NE0];
__device__ int g_esrc1[NE1];
__device__ int g_part0[NBLK0];
__device__ int g_part1[NBLK1];

// ---------------------------------------------------------------------------
// Zero the per-dst edge counters
// ---------------------------------------------------------------------------
__global__ void zero_cnt_kernel() {
    int stride = gridDim.x * blockDim.x;
    int i0 = blockIdx.x * blockDim.x + threadIdx.x;
    for (int i = i0; i < N_DST0; i += stride) g_cnt0[i] = 0;
    for (int i = i0; i < N_DST1; i += stride) g_cnt1[i] = 0;
}

// ---------------------------------------------------------------------------
// Fused: edge counting (first NCNT_BLK blocks) + x fp32->fp16 conversion
// (remaining blocks). The two jobs are independent; fusing overlaps the
// short atomic burst with the long streaming convert.
// ---------------------------------------------------------------------------
__global__ __launch_bounds__(256) void count_convert_kernel(
    const float* __restrict__ x,
    const int*   __restrict__ dst0,
    const int*   __restrict__ dst1)
{
    int bid = blockIdx.x;
    if (bid < NCNT_BLK) {
        int e = bid * 256 + threadIdx.x;
        if (e < NE0)            atomicAdd(&g_cnt0[dst0[e]], 1);
        else if (e < NE0 + NE1) atomicAdd(&g_cnt1[dst1[e - NE0]], 1);
    } else {
        size_t i = (size_t)(bid - NCNT_BLK) * 256 + threadIdx.x;
        const float4* x4 = (const float4*)x;
        float4 a = x4[2 * i];
        float4 b = x4[2 * i + 1];
        __half2 h0 = __floats2half2_rn(a.x, a.y);
        __half2 h1 = __floats2half2_rn(a.z, a.w);
        __half2 h2 = __floats2half2_rn(b.x, b.y);
        __half2 h3 = __floats2half2_rn(b.z, b.w);
        uint4 o;
        o.x = *(uint32_t*)&h0; o.y = *(uint32_t*)&h1;
        o.z = *(uint32_t*)&h2; o.w = *(uint32_t*)&h3;
        ((uint4*)g_xh)[i] = o;
    }
}

// ---------------------------------------------------------------------------
// Hierarchical scan (2 phases), fill
// ---------------------------------------------------------------------------
__global__ __launch_bounds__(512) void scan_a_kernel() {
    const int* cnt; int* rowptr; int* part; int n; int b;
    if ((int)blockIdx.x < NBLK0) {
        cnt = g_cnt0; rowptr = g_rowptr0; part = g_part0; n = N_DST0; b = blockIdx.x;
    } else {
        cnt = g_cnt1; rowptr = g_rowptr1; part = g_part1; n = N_DST1; b = blockIdx.x - NBLK0;
    }

    __shared__ int wsum[16];
    const int tid  = threadIdx.x;
    const int lane = tid & 31;
    const int wid  = tid >> 5;
    const int idx0 = b * SCAN_CHUNK + tid * 8;

    int v[8];
    if (idx0 + 8 <= n) {
        int4 a = *(const int4*)(cnt + idx0);
        int4 c = *(const int4*)(cnt + idx0 + 4);
        v[0]=a.x; v[1]=a.y; v[2]=a.z; v[3]=a.w;
        v[4]=c.x; v[5]=c.y; v[6]=c.z; v[7]=c.w;
    } else {
        #pragma unroll
        for (int j = 0; j < 8; ++j) v[j] = (idx0 + j < n) ? cnt[idx0 + j] : 0;
    }
    int incl[8]; int tot = 0;
    #pragma unroll
    for (int j = 0; j < 8; ++j) { tot += v[j]; incl[j] = tot; }

    int wincl = tot;
    #pragma unroll
    for (int o = 1; o < 32; o <<= 1) {
        int t = __shfl_up_sync(0xFFFFFFFFu, wincl, o);
        if (lane >= o) wincl += t;
    }
    if (lane == 31) wsum[wid] = wincl;
    __syncthreads();
    if (tid == 0) {
        int running = 0;
        #pragma unroll
        for (int w = 0; w < 16; ++w) { int t = wsum[w]; wsum[w] = running; running += t; }
        part[b] = running;
    }
    __syncthreads();

    int myexcl = wsum[wid] + (wincl - tot);
    if (idx0 + 8 <= n) {
        int4 r0 = make_int4(myexcl + incl[0]-v[0], myexcl + incl[1]-v[1],
                            myexcl + incl[2]-v[2], myexcl + incl[3]-v[3]);
        int4 r1 = make_int4(myexcl + incl[4]-v[4], myexcl + incl[5]-v[5],
                            myexcl + incl[6]-v[6], myexcl + incl[7]-v[7]);
        *(int4*)(rowptr + idx0)     = r0;
        *(int4*)(rowptr + idx0 + 4) = r1;
    } else {
        #pragma unroll
        for (int j = 0; j < 8; ++j)
            if (idx0 + j < n) rowptr[idx0 + j] = myexcl + incl[j] - v[j];
    }
}

__global__ __launch_bounds__(512) void scan_b_kernel() {
    int* rowptr; int* cur; const int* part; int n, nblk, b;
    if ((int)blockIdx.x < NBLK0) {
        rowptr = g_rowptr0; cur = g_cur0; part = g_part0;
        n = N_DST0; nblk = NBLK0; b = blockIdx.x;
    } else {
        rowptr = g_rowptr1; cur = g_cur1; part = g_part1;
        n = N_DST1; nblk = NBLK1; b = blockIdx.x - NBLK0;
    }
    int off = 0;
    for (int k = 0; k < b; ++k) off += part[k];

    const int tid  = threadIdx.x;
    const int idx0 = b * SCAN_CHUNK + tid * 8;
    if (idx0 + 8 <= n) {
        int4 a = *(const int4*)(rowptr + idx0);
        int4 c = *(const int4*)(rowptr + idx0 + 4);
        a.x += off; a.y += off; a.z += off; a.w += off;
        c.x += off; c.y += off; c.z += off; c.w += off;
        *(int4*)(rowptr + idx0)     = a;
        *(int4*)(rowptr + idx0 + 4) = c;
        *(int4*)(cur + idx0)        = a;
        *(int4*)(cur + idx0 + 4)    = c;
    } else {
        #pragma unroll
        for (int j = 0; j < 8; ++j) {
            int i = idx0 + j;
            if (i < n) { int e = rowptr[i] + off; rowptr[i] = e; cur[i] = e; }
        }
    }
    if (b == nblk - 1 && tid == 0) rowptr[n] = off + part[b];
}

__global__ void fill_kernel(const int* __restrict__ src0,
                            const int* __restrict__ dst0,
                            const int* __restrict__ src1,
                            const int* __restrict__ dst1) {
    int e = blockIdx.x * blockDim.x + threadIdx.x;
    if (e < NE0) {
        int p = atomicAdd(&g_cur0[dst0[e]], 1);
        g_esrc0[p] = src0[e];
    } else if (e < NE0 + NE1) {
        int e1 = e - NE0;
        int p = atomicAdd(&g_cur1[dst1[e1]], 1);
        g_esrc1[p] = src1[e1];
    }
}

// ---------------------------------------------------------------------------
// Pull gather (fp16 source): agg[d,:] = sum_e feat[esrc[e], :]
// 32 threads per dst row (one uint4 = 8 halves each), 4 rows per block.
// 4-edge unroll for MLP. fp32 accumulation.
// WHICH=0: xh -> agg0 ; WHICH=1: h0h -> agg1
// ---------------------------------------------------------------------------
template <int WHICH>
__global__ __launch_bounds__(128) void gather_kernel() {
    const __half* feat = WHICH ? g_h0h : g_xh;
    float* agg         = WHICH ? g_agg1 : g_agg0;
    const int* rowptr  = WHICH ? g_rowptr1 : g_rowptr0;
    const int* esrc    = WHICH ? g_esrc1 : g_esrc0;
    const int ndst     = WHICH ? N_DST1 : N_DST0;

    int d = blockIdx.x * 4 + (threadIdx.x >> 5);
    int lane = threadIdx.x & 31;
    if (d >= ndst) return;

    int beg = rowptr[d], end = rowptr[d + 1];
    float a0=0.f,a1=0.f,a2=0.f,a3=0.f,a4=0.f,a5=0.f,a6=0.f,a7=0.f;
    const uint4* f16 = (const uint4*)feat;

    #define ACCUM(v) do {                                           \
        float2 _f;                                                  \
        _f = __half22float2(*(__half2*)&(v).x); a0 += _f.x; a1 += _f.y; \
        _f = __half22float2(*(__half2*)&(v).y); a2 += _f.x; a3 += _f.y; \
        _f = __half22float2(*(__half2*)&(v).z); a4 += _f.x; a5 += _f.y; \
        _f = __half22float2(*(__half2*)&(v).w); a6 += _f.x; a7 += _f.y; \
    } while (0)

    int i = beg;
    for (; i + 3 < end; i += 4) {
        int s0 = esrc[i], s1 = esrc[i + 1], s2 = esrc[i + 2], s3 = esrc[i + 3];
        uint4 v0 = f16[(size_t)s0 * 32 + lane];
        uint4 v1 = f16[(size_t)s1 * 32 + lane];
        uint4 v2 = f16[(size_t)s2 * 32 + lane];
        uint4 v3 = f16[(size_t)s3 * 32 + lane];
        ACCUM(v0); ACCUM(v1); ACCUM(v2); ACCUM(v3);
    }
    for (; i < end; ++i) {
        int s0 = esrc[i];
        uint4 v0 = f16[(size_t)s0 * 32 + lane];
        ACCUM(v0);
    }
    #undef ACCUM

    float* dst = agg + (size_t)d * DIM + lane * 8;
    *(float4*)(dst)     = make_float4(a0, a1, a2, a3);
    *(float4*)(dst + 4) = make_float4(a4, a5, a6, a7);
}

// ---------------------------------------------------------------------------
// fp16 tensor-core fused layer GEMM (fp32 accumulate).
// A(ch<8) comes from fp16 source (g_xh for layer0, g_h0h for layer1);
// A(ch>=8) = fp32 agg (converted on stage); B converted from fp32 weights.
// Layer0 writes g_h0h (fp16); layer1 writes g_h1 fp32 + mirror.
// ---------------------------------------------------------------------------
__device__ __forceinline__ __half2 f2h2(float a, float b) {
    return __floats2half2_rn(a, b);
}

template <int LAYER>
__global__ __launch_bounds__(256) void layer_kernel(
    const float* __restrict__ W,      // [4,64,64]
    const float* __restrict__ loopw,  // [256,256]
    const float* __restrict__ bias,   // [256]
    float*       __restrict__ out2,   // layer1: mirror to d_out region
    int M)
{
    const float*  agg = (LAYER == 0) ? g_agg0 : g_agg1;
    const __half* xdh = (LAYER == 0) ? g_xh   : g_h0h;

    __shared__ __half As[128][40];   // 128 rows x 32 k  (pad -> 40)
    __shared__ __half Bs[32][72];    // 32 k x 64 n      (pad -> 72)

    const int cb  = blockIdx.x;        // output column block (0..3)
    const int r0  = blockIdx.y * 128;
    const int tid = threadIdx.x;
    const int lane = tid & 31;
    const int w   = tid >> 5;
    const int wm  = w & 3;             // warp row (4)
    const int wn  = w >> 2;            // warp col (2)
    const int t4  = lane >> 2;         // 0..7 (group)
    const int tc  = lane & 3;          // 0..3

    float acc[2][4][4];
    #pragma unroll
    for (int mt = 0; mt < 2; ++mt)
        #pragma unroll
        for (int nt = 0; nt < 4; ++nt)
            #pragma unroll
            for (int i = 0; i < 4; ++i) acc[mt][nt][i] = 0.f;

    for (int ch = 0; ch < 10; ++ch) {
        const int akbase = (ch < 8) ? ch * 32 : cb * 64 + (ch - 8) * 32;

        // ---- stage A tile into registers: 2 uint4 (8 halves each) / thread ----
        uint4 areg[2];
        #pragma unroll
        for (int l = 0; l < 2; ++l) {
            int idx = tid + l * 256;        // 0..511
            int row = idx >> 2;             // 0..127
            int q   = idx & 3;              // 8-half column group
            bool ok = (r0 + row < M);
            if (ch < 8) {
                areg[l] = ok ? *(const uint4*)(xdh + (size_t)(r0 + row) * DIM + akbase + q * 8)
                             : make_uint4(0u, 0u, 0u, 0u);
            } else {
                float4 fa = make_float4(0.f,0.f,0.f,0.f), fb = fa;
                if (ok) {
                    const float* p = agg + (size_t)(r0 + row) * DIM + akbase + q * 8;
                    fa = *(const float4*)p;
                    fb = *(const float4*)(p + 4);
                }
                __half2 h0 = f2h2(fa.x, fa.y), h1 = f2h2(fa.z, fa.w);
                __half2 h2 = f2h2(fb.x, fb.y), h3 = f2h2(fb.z, fb.w);
                areg[l].x = *(uint32_t*)&h0; areg[l].y = *(uint32_t*)&h1;
                areg[l].z = *(uint32_t*)&h2; areg[l].w = *(uint32_t*)&h3;
            }
        }
        // ---- stage B tile: 8 halves / thread ----
        uint4 breg;
        {
            int k = tid >> 3;
            int q = tid & 7;
            const float* p = (ch < 8)
                ? loopw + (size_t)(ch * 32 + k) * DIM + cb * 64 + q * 8
                : W + (size_t)cb * BD * BD + (size_t)((ch - 8) * 32 + k) * BD + q * 8;
            float4 fa = *(const float4*)p;
            float4 fb = *(const float4*)(p + 4);
            __half2 h0 = f2h2(fa.x, fa.y), h1 = f2h2(fa.z, fa.w);
            __half2 h2 = f2h2(fb.x, fb.y), h3 = f2h2(fb.z, fb.w);
            breg.x = *(uint32_t*)&h0; breg.y = *(uint32_t*)&h1;
            breg.z = *(uint32_t*)&h2; breg.w = *(uint32_t*)&h3;
        }

        __syncthreads();   // previous chunk compute done

        #pragma unroll
        for (int l = 0; l < 2; ++l) {
            int idx = tid + l * 256;
            int row = idx >> 2;
            int q   = idx & 3;
            *(uint4*)&As[row][q * 8] = areg[l];
        }
        {
            int k = tid >> 3;
            int q = tid & 7;
            *(uint4*)&Bs[k][q * 8] = breg;
        }
        __syncthreads();

        // ---- compute: 2 k-steps of 16 ----
        #pragma unroll
        for (int ks = 0; ks < 2; ++ks) {
            const int kb = ks * 16;
            uint32_t a[2][4];
            #pragma unroll
            for (int mt = 0; mt < 2; ++mt) {
                int mrow = wm * 32 + mt * 16 + t4;
                a[mt][0] = *(const uint32_t*)&As[mrow][kb + 2 * tc];
                a[mt][1] = *(const uint32_t*)&As[mrow + 8][kb + 2 * tc];
                a[mt][2] = *(const uint32_t*)&As[mrow][kb + 2 * tc + 8];
                a[mt][3] = *(const uint32_t*)&As[mrow + 8][kb + 2 * tc + 8];
            }
            #pragma unroll
            for (int nt = 0; nt < 4; ++nt) {
                int ncol = wn * 32 + nt * 8 + t4;
                uint32_t b0 = (uint32_t)*(const uint16_t*)&Bs[kb + 2 * tc][ncol]
                            | ((uint32_t)*(const uint16_t*)&Bs[kb + 2 * tc + 1][ncol] << 16);
                uint32_t b1 = (uint32_t)*(const uint16_t*)&Bs[kb + 2 * tc + 8][ncol]
                            | ((uint32_t)*(const uint16_t*)&Bs[kb + 2 * tc + 9][ncol] << 16);
                #pragma unroll
                for (int mt = 0; mt < 2; ++mt) {
                    asm volatile(
                        "mma.sync.aligned.m16n8k16.row.col.f32.f16.f16.f32 "
                        "{%0,%1,%2,%3}, {%4,%5,%6,%7}, {%8,%9}, {%0,%1,%2,%3};\n"
                        : "+f"(acc[mt][nt][0]), "+f"(acc[mt][nt][1]),
                          "+f"(acc[mt][nt][2]), "+f"(acc[mt][nt][3])
                        : "r"(a[mt][0]), "r"(a[mt][1]), "r"(a[mt][2]), "r"(a[mt][3]),
                          "r"(b0), "r"(b1));
                }
            }
        }
        __syncthreads();
    }

    // ---- epilogue: bias + relu ----
    #pragma unroll
    for (int nt = 0; nt < 4; ++nt) {
        int c = cb * 64 + wn * 32 + nt * 8 + 2 * tc;
        float2 bb = *(const float2*)(bias + c);
        #pragma unroll
        for (int mt = 0; mt < 2; ++mt) {
            int r = r0 + wm * 32 + mt * 16 + t4;
            float ox0 = fmaxf(acc[mt][nt][0] + bb.x, 0.f);
            float oy0 = fmaxf(acc[mt][nt][1] + bb.y, 0.f);
            float ox1 = fmaxf(acc[mt][nt][2] + bb.x, 0.f);
            float oy1 = fmaxf(acc[mt][nt][3] + bb.y, 0.f);
            if (LAYER == 0) {
                if (r < M)
                    *(__half2*)(g_h0h + (size_t)r * DIM + c) = f2h2(ox0, oy0);
                if (r + 8 < M)
                    *(__half2*)(g_h0h + (size_t)(r + 8) * DIM + c) = f2h2(ox1, oy1);
            } else {
                if (r < M) {
                    float2 o = make_float2(ox0, oy0);
                    *(float2*)(g_h1 + (size_t)r * DIM + c) = o;
                    *(float2*)(out2 + (size_t)r * DIM + c) = o;
                }
                if (r + 8 < M) {
                    float2 o = make_float2(ox1, oy1);
                    *(float2*)(g_h1 + (size_t)(r + 8) * DIM + c) = o;
                    *(float2*)(out2 + (size_t)(r + 8) * DIM + c) = o;
                }
            }
        }
    }
}

// ---------------------------------------------------------------------------
// Link predictor, batched: 32 pairs per 128-thread block.
// ---------------------------------------------------------------------------
#define PPB 32
__global__ __launch_bounds__(128) void pred_kernel(
    const int*   __restrict__ ps, const int* __restrict__ pd,
    const int*   __restrict__ ns, const int* __restrict__ nd,
    const float* __restrict__ pw1,    // [256, 128]
    const float* __restrict__ pb1,    // [128]
    const float* __restrict__ pw2,    // [128]
    const float* __restrict__ pb2,    // [1]
    float*       __restrict__ out)    // [10000] : pos then neg
{
    const float* h = g_h1;
    __shared__ float es[PPB][256];
    __shared__ int   sa[PPB], sb[PPB];
    __shared__ float s_part[4][PPB];

    int tid  = threadIdx.x;
    int lane = tid & 31;
    int wid  = tid >> 5;
    int pbase = blockIdx.x * PPB;

    if (tid < PPB) {
        int P = pbase + tid;
        int a = 0, b = 0;
        if (P < NPTOT) {
            if (P < NPAIR) { a = ps[P]; b = pd[P]; }
            else           { a = ns[P - NPAIR]; b = nd[P - NPAIR]; }
        }
        sa[tid] = a; sb[tid] = b;
    }
    __syncthreads();

    #pragma unroll 4
    for (int p = 0; p < PPB; ++p) {
        int a = sa[p], b = sb[p];
        es[p][tid]       = h[(size_t)a * DIM + tid]       * h[(size_t)b * DIM + tid];
        es[p][tid + 128] = h[(size_t)a * DIM + 128 + tid] * h[(size_t)b * DIM + 128 + tid];
    }
    __syncthreads();

    float acc[PPB];
    #pragma unroll
    for (int p = 0; p < PPB; ++p) acc[p] = 0.f;

    for (int j = 0; j < 256; j += 4) {
        float w0 = pw1[(j + 0) * 128 + tid];
        float w1 = pw1[(j + 1) * 128 + tid];
        float w2 = pw1[(j + 2) * 128 + tid];
        float w3 = pw1[(j + 3) * 128 + tid];
        #pragma unroll
        for (int p = 0; p < PPB; ++p) {
            float4 e4 = *(const float4*)&es[p][j];
            acc[p] += e4.x * w0 + e4.y * w1 + e4.z * w2 + e4.w * w3;
        }
    }

    float pb  = pb1[tid];
    float w2v = pw2[tid];
    #pragma unroll
    for (int p = 0; p < PPB; ++p) {
        float v = fmaxf(acc[p] + pb, 0.f) * w2v;
        #pragma unroll
        for (int o = 16; o; o >>= 1) v += __shfl_xor_sync(0xFFFFFFFFu, v, o);
        if (lane == 0) s_part[wid][p] = v;
    }
    __syncthreads();
    if (tid < PPB) {
        int P = pbase + tid;
        if (P < NPTOT)
            out[P] = s_part[0][tid] + s_part[1][tid] + s_part[2][tid] + s_part[3][tid]
                   + pb2[0];
    }
}

// ---------------------------------------------------------------------------
// Launch
// ---------------------------------------------------------------------------
extern "C" void kernel_launch(void* const* d_in, const int* in_sizes, int n_in,
                              void* d_out, int out_size)
{
    const float* x     = (const float*)d_in[0];
    const int*   src0  = (const int*)d_in[1];
    const int*   dst0  = (const int*)d_in[2];
    const int*   src1  = (const int*)d_in[3];
    const int*   dst1  = (const int*)d_in[4];
    const int*   psrc  = (const int*)d_in[5];
    const int*   pdst  = (const int*)d_in[6];
    const int*   nsrc  = (const int*)d_in[7];
    const int*   ndst  = (const int*)d_in[8];
    const float* W0    = (const float*)d_in[9];
    const float* loop0 = (const float*)d_in[10];
    const float* b0    = (const float*)d_in[11];
    const float* W1    = (const float*)d_in[12];
    const float* loop1 = (const float*)d_in[13];
    const float* b1    = (const float*)d_in[14];
    const float* pw1   = (const float*)d_in[15];
    const float* pb1   = (const float*)d_in[16];
    const float* pw2   = (const float*)d_in[17];
    const float* pb2   = (const float*)d_in[18];
    float*       out   = (float*)d_out;

    // CSR build + fp16 staging (count fused with convert for overlap)
    zero_cnt_kernel<<<256, 256>>>();
    count_convert_kernel<<<NCNT_BLK + NCVT_BLK, 256>>>(x, dst0, dst1);
    scan_a_kernel<<<NBLK0 + NBLK1, 512>>>();
    scan_b_kernel<<<NBLK0 + NBLK1, 512>>>();
    fill_kernel<<<(NE0 + NE1 + 255) / 256, 256>>>(src0, dst0, src1, dst1);

    // layer 0: pull-aggregate xh (fp16), fused fp16-mma transform -> h0 (fp16)
    gather_kernel<0><<<(N_DST0 + 3) / 4, 128>>>();
    {
        dim3 grid(NBASE, (N_DST0 + 127) / 128);
        layer_kernel<0><<<grid, 256>>>(W0, loop0, b0, nullptr, N_DST0);
    }

    // layer 1: pull-aggregate h0h (fp16), fused transform -> h1 (+mirror to out)
    gather_kernel<1><<<(N_DST1 + 3) / 4, 128>>>();
    {
        dim3 grid(NBASE, (N_DST1 + 127) / 128);
        layer_kernel<1><<<grid, 256>>>(W1, loop1, b1, out + NPTOT, N_DST1);
    }

    // link prediction -> out[0:5000] (pos), out[5000:10000] (neg)
    pred_kernel<<<(NPTOT + PPB - 1) / PPB, 128>>>(psrc, pdst, nsrc, ndst,
                                                  pw1, pb1, pw2, pb2, out);
}

// round 11
// speedup vs baseline: 1.5683x; 1.0388x over previous
#include <cuda_runtime.h>
#include <cuda_fp16.h>
#include <stdint.h>

// Problem constants
#define N_SRC0 200000
#define N_DST0 50000
#define N_DST1 10000
#define NE0    800000
#define NE1    160000
#define DIM    256
#define NBASE  4
#define BD     64
#define NPAIR  5000
#define NPTOT  (2 * NPAIR)

#define SCAN_CHUNK 4096
#define NBLK0 ((N_DST0 + SCAN_CHUNK - 1) / SCAN_CHUNK)   // 13
#define NBLK1 ((N_DST1 + SCAN_CHUNK - 1) / SCAN_CHUNK)   // 3

#define NEDGE_BLK ((NE0 + NE1 + 255) / 256)              // 3750 (count / fill)
#define NCVT_TOT  ((N_SRC0 * (DIM / 8)) / 256)           // 25000 convert blocks
#define NCVT_H    (NCVT_TOT / 2)                         // 12500 per half

// ---------------------------------------------------------------------------
// Scratch (__device__ globals; kernels reference them directly)
// ---------------------------------------------------------------------------
__device__ __align__(16) __half g_agg0h[(size_t)N_DST0 * DIM];
__device__ __align__(16) __half g_agg1h[(size_t)N_DST1 * DIM];
__device__ __align__(16) __half g_h0h[(size_t)N_DST0 * DIM];
__device__ float  g_h1[(size_t)N_DST1 * DIM];
__device__ __align__(16) __half g_xh[(size_t)N_SRC0 * DIM];

__device__ __align__(16) int g_cnt0[N_DST0];
__device__ __align__(16) int g_cnt1[N_DST1];
__device__ __align__(16) int g_rowptr0[N_DST0 + 1];
__device__ __align__(16) int g_rowptr1[N_DST1 + 1];
__device__ __align__(16) int g_cur0[N_DST0];
__device__ __align__(16) int g_cur1[N_DST1];
__device__ int g_esrc0[NE0];
__device__ int g_esrc1[NE1];
__device__ int g_part0[NBLK0];
__device__ int g_part1[NBLK1];

// ---------------------------------------------------------------------------
// Convert helper: one block converts 256*8 floats starting at uint4 index base
// ---------------------------------------------------------------------------
__device__ __forceinline__ void convert_block(const float* __restrict__ x,
                                              size_t blk) {
    size_t i = blk * 256 + threadIdx.x;
    const float4* x4 = (const float4*)x;
    float4 a = x4[2 * i];
    float4 b = x4[2 * i + 1];
    __half2 h0 = __floats2half2_rn(a.x, a.y);
    __half2 h1 = __floats2half2_rn(a.z, a.w);
    __half2 h2 = __floats2half2_rn(b.x, b.y);
    __half2 h3 = __floats2half2_rn(b.z, b.w);
    uint4 o;
    o.x = *(uint32_t*)&h0; o.y = *(uint32_t*)&h1;
    o.z = *(uint32_t*)&h2; o.w = *(uint32_t*)&h3;
    ((uint4*)g_xh)[i] = o;
}

// ---------------------------------------------------------------------------
// Zero per-dst edge counters
// ---------------------------------------------------------------------------
__global__ void zero_cnt_kernel() {
    int stride = gridDim.x * blockDim.x;
    int i0 = blockIdx.x * blockDim.x + threadIdx.x;
    for (int i = i0; i < N_DST0; i += stride) g_cnt0[i] = 0;
    for (int i = i0; i < N_DST1; i += stride) g_cnt1[i] = 0;
}

// ---------------------------------------------------------------------------
// Fused: edge counting + first half of x conversion
// ---------------------------------------------------------------------------
__global__ __launch_bounds__(256) void count_convert_kernel(
    const float* __restrict__ x,
    const int*   __restrict__ dst0,
    const int*   __restrict__ dst1)
{
    int bid = blockIdx.x;
    if (bid < NEDGE_BLK) {
        int e = bid * 256 + threadIdx.x;
        if (e < NE0)            atomicAdd(&g_cnt0[dst0[e]], 1);
        else if (e < NE0 + NE1) atomicAdd(&g_cnt1[dst1[e - NE0]], 1);
    } else {
        convert_block(x, (size_t)(bid - NEDGE_BLK));
    }
}

// ---------------------------------------------------------------------------
// Hierarchical scan (2 phases)
// ---------------------------------------------------------------------------
__global__ __launch_bounds__(512) void scan_a_kernel() {
    const int* cnt; int* rowptr; int* part; int n; int b;
    if ((int)blockIdx.x < NBLK0) {
        cnt = g_cnt0; rowptr = g_rowptr0; part = g_part0; n = N_DST0; b = blockIdx.x;
    } else {
        cnt = g_cnt1; rowptr = g_rowptr1; part = g_part1; n = N_DST1; b = blockIdx.x - NBLK0;
    }

    __shared__ int wsum[16];
    const int tid  = threadIdx.x;
    const int lane = tid & 31;
    const int wid  = tid >> 5;
    const int idx0 = b * SCAN_CHUNK + tid * 8;

    int v[8];
    if (idx0 + 8 <= n) {
        int4 a = *(const int4*)(cnt + idx0);
        int4 c = *(const int4*)(cnt + idx0 + 4);
        v[0]=a.x; v[1]=a.y; v[2]=a.z; v[3]=a.w;
        v[4]=c.x; v[5]=c.y; v[6]=c.z; v[7]=c.w;
    } else {
        #pragma unroll
        for (int j = 0; j < 8; ++j) v[j] = (idx0 + j < n) ? cnt[idx0 + j] : 0;
    }
    int incl[8]; int tot = 0;
    #pragma unroll
    for (int j = 0; j < 8; ++j) { tot += v[j]; incl[j] = tot; }

    int wincl = tot;
    #pragma unroll
    for (int o = 1; o < 32; o <<= 1) {
        int t = __shfl_up_sync(0xFFFFFFFFu, wincl, o);
        if (lane >= o) wincl += t;
    }
    if (lane == 31) wsum[wid] = wincl;
    __syncthreads();
    if (tid == 0) {
        int running = 0;
        #pragma unroll
        for (int w = 0; w < 16; ++w) { int t = wsum[w]; wsum[w] = running; running += t; }
        part[b] = running;
    }
    __syncthreads();

    int myexcl = wsum[wid] + (wincl - tot);
    if (idx0 + 8 <= n) {
        int4 r0 = make_int4(myexcl + incl[0]-v[0], myexcl + incl[1]-v[1],
                            myexcl + incl[2]-v[2], myexcl + incl[3]-v[3]);
        int4 r1 = make_int4(myexcl + incl[4]-v[4], myexcl + incl[5]-v[5],
                            myexcl + incl[6]-v[6], myexcl + incl[7]-v[7]);
        *(int4*)(rowptr + idx0)     = r0;
        *(int4*)(rowptr + idx0 + 4) = r1;
    } else {
        #pragma unroll
        for (int j = 0; j < 8; ++j)
            if (idx0 + j < n) rowptr[idx0 + j] = myexcl + incl[j] - v[j];
    }
}

__global__ __launch_bounds__(512) void scan_b_kernel() {
    int* rowptr; int* cur; const int* part; int n, nblk, b;
    if ((int)blockIdx.x < NBLK0) {
        rowptr = g_rowptr0; cur = g_cur0; part = g_part0;
        n = N_DST0; nblk = NBLK0; b = blockIdx.x;
    } else {
        rowptr = g_rowptr1; cur = g_cur1; part = g_part1;
        n = N_DST1; nblk = NBLK1; b = blockIdx.x - NBLK0;
    }
    int off = 0;
    for (int k = 0; k < b; ++k) off += part[k];

    const int tid  = threadIdx.x;
    const int idx0 = b * SCAN_CHUNK + tid * 8;
    if (idx0 + 8 <= n) {
        int4 a = *(const int4*)(rowptr + idx0);
        int4 c = *(const int4*)(rowptr + idx0 + 4);
        a.x += off; a.y += off; a.z += off; a.w += off;
        c.x += off; c.y += off; c.z += off; c.w += off;
        *(int4*)(rowptr + idx0)     = a;
        *(int4*)(rowptr + idx0 + 4) = c;
        *(int4*)(cur + idx0)        = a;
        *(int4*)(cur + idx0 + 4)    = c;
    } else {
        #pragma unroll
        for (int j = 0; j < 8; ++j) {
            int i = idx0 + j;
            if (i < n) { int e = rowptr[i] + off; rowptr[i] = e; cur[i] = e; }
        }
    }
    if (b == nblk - 1 && tid == 0) rowptr[n] = off + part[b];
}

// ---------------------------------------------------------------------------
// Fused: CSR fill + second half of x conversion
// ---------------------------------------------------------------------------
__global__ __launch_bounds__(256) void fill_convert_kernel(
    const float* __restrict__ x,
    const int* __restrict__ src0, const int* __restrict__ dst0,
    const int* __restrict__ src1, const int* __restrict__ dst1)
{
    int bid = blockIdx.x;
    if (bid < NEDGE_BLK) {
        int e = bid * 256 + threadIdx.x;
        if (e < NE0) {
            int p = atomicAdd(&g_cur0[dst0[e]], 1);
            g_esrc0[p] = src0[e];
        } else if (e < NE0 + NE1) {
            int e1 = e - NE0;
            int p = atomicAdd(&g_cur1[dst1[e1]], 1);
            g_esrc1[p] = src1[e1];
        }
    } else {
        convert_block(x, (size_t)(bid - NEDGE_BLK) + NCVT_H);
    }
}

// ---------------------------------------------------------------------------
// Pull gather (fp16 source -> fp16 agg, fp32 accumulation in registers).
// 32 threads per dst row (one uint4 = 8 halves each), 4 rows per block.
// WHICH=0: xh -> agg0h ; WHICH=1: h0h -> agg1h
// ---------------------------------------------------------------------------
template <int WHICH>
__global__ __launch_bounds__(128) void gather_kernel() {
    const __half* feat = WHICH ? g_h0h : g_xh;
    __half* agg        = WHICH ? g_agg1h : g_agg0h;
    const int* rowptr  = WHICH ? g_rowptr1 : g_rowptr0;
    const int* esrc    = WHICH ? g_esrc1 : g_esrc0;
    const int ndst     = WHICH ? N_DST1 : N_DST0;

    int d = blockIdx.x * 4 + (threadIdx.x >> 5);
    int lane = threadIdx.x & 31;
    if (d >= ndst) return;

    int beg = rowptr[d], end = rowptr[d + 1];
    float a0=0.f,a1=0.f,a2=0.f,a3=0.f,a4=0.f,a5=0.f,a6=0.f,a7=0.f;
    const uint4* f16 = (const uint4*)feat;

    #define ACCUM(v) do {                                           \
        float2 _f;                                                  \
        _f = __half22float2(*(__half2*)&(v).x); a0 += _f.x; a1 += _f.y; \
        _f = __half22float2(*(__half2*)&(v).y); a2 += _f.x; a3 += _f.y; \
        _f = __half22float2(*(__half2*)&(v).z); a4 += _f.x; a5 += _f.y; \
        _f = __half22float2(*(__half2*)&(v).w); a6 += _f.x; a7 += _f.y; \
    } while (0)

    int i = beg;
    for (; i + 3 < end; i += 4) {
        int s0 = esrc[i], s1 = esrc[i + 1], s2 = esrc[i + 2], s3 = esrc[i + 3];
        uint4 v0 = f16[(size_t)s0 * 32 + lane];
        uint4 v1 = f16[(size_t)s1 * 32 + lane];
        uint4 v2 = f16[(size_t)s2 * 32 + lane];
        uint4 v3 = f16[(size_t)s3 * 32 + lane];
        ACCUM(v0); ACCUM(v1); ACCUM(v2); ACCUM(v3);
    }
    for (; i < end; ++i) {
        int s0 = esrc[i];
        uint4 v0 = f16[(size_t)s0 * 32 + lane];
        ACCUM(v0);
    }
    #undef ACCUM

    __half2 o0 = __floats2half2_rn(a0, a1);
    __half2 o1 = __floats2half2_rn(a2, a3);
    __half2 o2 = __floats2half2_rn(a4, a5);
    __half2 o3 = __floats2half2_rn(a6, a7);
    uint4 ov;
    ov.x = *(uint32_t*)&o0; ov.y = *(uint32_t*)&o1;
    ov.z = *(uint32_t*)&o2; ov.w = *(uint32_t*)&o3;
    ((uint4*)agg)[(size_t)d * 32 + lane] = ov;
}

// ---------------------------------------------------------------------------
// fp16 tensor-core fused layer GEMM (fp32 accumulate).
// All A chunks now fp16: xdh (ch<8) and aggh (ch>=8). B from fp32 weights.
// Layer0 writes g_h0h (fp16); layer1 writes g_h1 fp32 + mirror.
// ---------------------------------------------------------------------------
__device__ __forceinline__ __half2 f2h2(float a, float b) {
    return __floats2half2_rn(a, b);
}

template <int LAYER>
__global__ __launch_bounds__(256) void layer_kernel(
    const float* __restrict__ W,      // [4,64,64]
    const float* __restrict__ loopw,  // [256,256]
    const float* __restrict__ bias,   // [256]
    float*       __restrict__ out2,   // layer1: mirror to d_out region
    int M)
{
    const __half* aggh = (LAYER == 0) ? g_agg0h : g_agg1h;
    const __half* xdh  = (LAYER == 0) ? g_xh   : g_h0h;

    __shared__ __half As[128][40];   // 128 rows x 32 k  (pad -> 40)
    __shared__ __half Bs[32][72];    // 32 k x 64 n      (pad -> 72)

    const int cb  = blockIdx.x;        // output column block (0..3)
    const int r0  = blockIdx.y * 128;
    const int tid = threadIdx.x;
    const int lane = tid & 31;
    const int w   = tid >> 5;
    const int wm  = w & 3;             // warp row (4)
    const int wn  = w >> 2;            // warp col (2)
    const int t4  = lane >> 2;         // 0..7 (group)
    const int tc  = lane & 3;          // 0..3

    float acc[2][4][4];
    #pragma unroll
    for (int mt = 0; mt < 2; ++mt)
        #pragma unroll
        for (int nt = 0; nt < 4; ++nt)
            #pragma unroll
            for (int i = 0; i < 4; ++i) acc[mt][nt][i] = 0.f;

    for (int ch = 0; ch < 10; ++ch) {
        const int akbase = (ch < 8) ? ch * 32 : cb * 64 + (ch - 8) * 32;
        const __half* amat = (ch < 8) ? xdh : aggh;

        // ---- stage A tile: 2 uint4 (8 halves each) / thread ----
        uint4 areg[2];
        #pragma unroll
        for (int l = 0; l < 2; ++l) {
            int idx = tid + l * 256;        // 0..511
            int row = idx >> 2;             // 0..127
            int q   = idx & 3;
            areg[l] = (r0 + row < M)
                ? *(const uint4*)(amat + (size_t)(r0 + row) * DIM + akbase + q * 8)
                : make_uint4(0u, 0u, 0u, 0u);
        }
        // ---- stage B tile: 8 halves / thread ----
        uint4 breg;
        {
            int k = tid >> 3;
            int q = tid & 7;
            const float* p = (ch < 8)
                ? loopw + (size_t)(ch * 32 + k) * DIM + cb * 64 + q * 8
                : W + (size_t)cb * BD * BD + (size_t)((ch - 8) * 32 + k) * BD + q * 8;
            float4 fa = *(const float4*)p;
            float4 fb = *(const float4*)(p + 4);
            __half2 h0 = f2h2(fa.x, fa.y), h1 = f2h2(fa.z, fa.w);
            __half2 h2 = f2h2(fb.x, fb.y), h3 = f2h2(fb.z, fb.w);
            breg.x = *(uint32_t*)&h0; breg.y = *(uint32_t*)&h1;
            breg.z = *(uint32_t*)&h2; breg.w = *(uint32_t*)&h3;
        }

        __syncthreads();   // previous chunk compute done

        #pragma unroll
        for (int l = 0; l < 2; ++l) {
            int idx = tid + l * 256;
            int row = idx >> 2;
            int q   = idx & 3;
            *(uint4*)&As[row][q * 8] = areg[l];
        }
        {
            int k = tid >> 3;
            int q = tid & 7;
            *(uint4*)&Bs[k][q * 8] = breg;
        }
        __syncthreads();

        // ---- compute: 2 k-steps of 16 ----
        #pragma unroll
        for (int ks = 0; ks < 2; ++ks) {
            const int kb = ks * 16;
            uint32_t a[2][4];
            #pragma unroll
            for (int mt = 0; mt < 2; ++mt) {
                int mrow = wm * 32 + mt * 16 + t4;
                a[mt][0] = *(const uint32_t*)&As[mrow][kb + 2 * tc];
                a[mt][1] = *(const uint32_t*)&As[mrow + 8][kb + 2 * tc];
                a[mt][2] = *(const uint32_t*)&As[mrow][kb + 2 * tc + 8];
                a[mt][3] = *(const uint32_t*)&As[mrow + 8][kb + 2 * tc + 8];
            }
            #pragma unroll
            for (int nt = 0; nt < 4; ++nt) {
                int ncol = wn * 32 + nt * 8 + t4;
                uint32_t b0 = (uint32_t)*(const uint16_t*)&Bs[kb + 2 * tc][ncol]
                            | ((uint32_t)*(const uint16_t*)&Bs[kb + 2 * tc + 1][ncol] << 16);
                uint32_t b1 = (uint32_t)*(const uint16_t*)&Bs[kb + 2 * tc + 8][ncol]
                            | ((uint32_t)*(const uint16_t*)&Bs[kb + 2 * tc + 9][ncol] << 16);
                #pragma unroll
                for (int mt = 0; mt < 2; ++mt) {
                    asm volatile(
                        "mma.sync.aligned.m16n8k16.row.col.f32.f16.f16.f32 "
                        "{%0,%1,%2,%3}, {%4,%5,%6,%7}, {%8,%9}, {%0,%1,%2,%3};\n"
                        : "+f"(acc[mt][nt][0]), "+f"(acc[mt][nt][1]),
                          "+f"(acc[mt][nt][2]), "+f"(acc[mt][nt][3])
                        : "r"(a[mt][0]), "r"(a[mt][1]), "r"(a[mt][2]), "r"(a[mt][3]),
                          "r"(b0), "r"(b1));
                }
            }
        }
        __syncthreads();
    }

    // ---- epilogue: bias + relu ----
    #pragma unroll
    for (int nt = 0; nt < 4; ++nt) {
        int c = cb * 64 + wn * 32 + nt * 8 + 2 * tc;
        float2 bb = *(const float2*)(bias + c);
        #pragma unroll
        for (int mt = 0; mt < 2; ++mt) {
            int r = r0 + wm * 32 + mt * 16 + t4;
            float ox0 = fmaxf(acc[mt][nt][0] + bb.x, 0.f);
            float oy0 = fmaxf(acc[mt][nt][1] + bb.y, 0.f);
            float ox1 = fmaxf(acc[mt][nt][2] + bb.x, 0.f);
            float oy1 = fmaxf(acc[mt][nt][3] + bb.y, 0.f);
            if (LAYER == 0) {
                if (r < M)
                    *(__half2*)(g_h0h + (size_t)r * DIM + c) = f2h2(ox0, oy0);
                if (r + 8 < M)
                    *(__half2*)(g_h0h + (size_t)(r + 8) * DIM + c) = f2h2(ox1, oy1);
            } else {
                if (r < M) {
                    float2 o = make_float2(ox0, oy0);
                    *(float2*)(g_h1 + (size_t)r * DIM + c) = o;
                    *(float2*)(out2 + (size_t)r * DIM + c) = o;
                }
                if (r + 8 < M) {
                    float2 o = make_float2(ox1, oy1);
                    *(float2*)(g_h1 + (size_t)(r + 8) * DIM + c) = o;
                    *(float2*)(out2 + (size_t)(r + 8) * DIM + c) = o;
                }
            }
        }
    }
}

// ---------------------------------------------------------------------------
// Link predictor, batched: 32 pairs per 128-thread block.
// ---------------------------------------------------------------------------
#define PPB 32
__global__ __launch_bounds__(128) void pred_kernel(
    const int*   __restrict__ ps, const int* __restrict__ pd,
    const int*   __restrict__ ns, const int* __restrict__ nd,
    const float* __restrict__ pw1,    // [256, 128]
    const float* __restrict__ pb1,    // [128]
    const float* __restrict__ pw2,    // [128]
    const float* __restrict__ pb2,    // [1]
    float*       __restrict__ out)    // [10000] : pos then neg
{
    const float* h = g_h1;
    __shared__ float es[PPB][256];
    __shared__ int   sa[PPB], sb[PPB];
    __shared__ float s_part[4][PPB];

    int tid  = threadIdx.x;
    int lane = tid & 31;
    int wid  = tid >> 5;
    int pbase = blockIdx.x * PPB;

    if (tid < PPB) {
        int P = pbase + tid;
        int a = 0, b = 0;
        if (P < NPTOT) {
            if (P < NPAIR) { a = ps[P]; b = pd[P]; }
            else           { a = ns[P - NPAIR]; b = nd[P - NPAIR]; }
        }
        sa[tid] = a; sb[tid] = b;
    }
    __syncthreads();

    #pragma unroll 4
    for (int p = 0; p < PPB; ++p) {
        int a = sa[p], b = sb[p];
        es[p][tid]       = h[(size_t)a * DIM + tid]       * h[(size_t)b * DIM + tid];
        es[p][tid + 128] = h[(size_t)a * DIM + 128 + tid] * h[(size_t)b * DIM + 128 + tid];
    }
    __syncthreads();

    float acc[PPB];
    #pragma unroll
    for (int p = 0; p < PPB; ++p) acc[p] = 0.f;

    for (int j = 0; j < 256; j += 4) {
        float w0 = pw1[(j + 0) * 128 + tid];
        float w1 = pw1[(j + 1) * 128 + tid];
        float w2 = pw1[(j + 2) * 128 + tid];
        float w3 = pw1[(j + 3) * 128 + tid];
        #pragma unroll
        for (int p = 0; p < PPB; ++p) {
            float4 e4 = *(const float4*)&es[p][j];
            acc[p] += e4.x * w0 + e4.y * w1 + e4.z * w2 + e4.w * w3;
        }
    }

    float pb  = pb1[tid];
    float w2v = pw2[tid];
    #pragma unroll
    for (int p = 0; p < PPB; ++p) {
        float v = fmaxf(acc[p] + pb, 0.f) * w2v;
        #pragma unroll
        for (int o = 16; o; o >>= 1) v += __shfl_xor_sync(0xFFFFFFFFu, v, o);
        if (lane == 0) s_part[wid][p] = v;
    }
    __syncthreads();
    if (tid < PPB) {
        int P = pbase + tid;
        if (P < NPTOT)
            out[P] = s_part[0][tid] + s_part[1][tid] + s_part[2][tid] + s_part[3][tid]
                   + pb2[0];
    }
}

// ---------------------------------------------------------------------------
// Launch
// ---------------------------------------------------------------------------
extern "C" void kernel_launch(void* const* d_in, const int* in_sizes, int n_in,
                              void* d_out, int out_size)
{
    const float* x     = (const float*)d_in[0];
    const int*   src0  = (const int*)d_in[1];
    const int*   dst0  = (const int*)d_in[2];
    const int*   src1  = (const int*)d_in[3];
    const int*   dst1  = (const int*)d_in[4];
    const int*   psrc  = (const int*)d_in[5];
    const int*   pdst  = (const int*)d_in[6];
    const int*   nsrc  = (const int*)d_in[7];
    const int*   ndst  = (const int*)d_in[8];
    const float* W0    = (const float*)d_in[9];
    const float* loop0 = (const float*)d_in[10];
    const float* b0    = (const float*)d_in[11];
    const float* W1    = (const float*)d_in[12];
    const float* loop1 = (const float*)d_in[13];
    const float* b1    = (const float*)d_in[14];
    const float* pw1   = (const float*)d_in[15];
    const float* pb1   = (const float*)d_in[16];
    const float* pw2   = (const float*)d_in[17];
    const float* pb2   = (const float*)d_in[18];
    float*       out   = (float*)d_out;

    // CSR build with x-conversion halves fused into count and fill
    zero_cnt_kernel<<<256, 256>>>();
    count_convert_kernel<<<NEDGE_BLK + NCVT_H, 256>>>(x, dst0, dst1);
    scan_a_kernel<<<NBLK0 + NBLK1, 512>>>();
    scan_b_kernel<<<NBLK0 + NBLK1, 512>>>();
    fill_convert_kernel<<<NEDGE_BLK + (NCVT_TOT - NCVT_H), 256>>>(
        x, src0, dst0, src1, dst1);

    // layer 0: pull-aggregate xh (fp16) -> agg0h, fused fp16-mma -> h0h
    gather_kernel<0><<<(N_DST0 + 3) / 4, 128>>>();
    {
        dim3 grid(NBASE, (N_DST0 + 127) / 128);
        layer_kernel<0><<<grid, 256>>>(W0, loop0, b0, nullptr, N_DST0);
    }

    // layer 1: pull-aggregate h0h -> agg1h, fused -> h1 (+mirror to out)
    gather_kernel<1><<<(N_DST1 + 3) / 4, 128>>>();
    {
        dim3 grid(NBASE, (N_DST1 + 127) / 128);
        layer_kernel<1><<<grid, 256>>>(W1, loop1, b1, out + NPTOT, N_DST1);
    }

    // link prediction -> out[0:5000] (pos), out[5000:10000] (neg)
    pred_kernel<<<(NPTOT + PPB - 1) / PPB, 128>>>(psrc, pdst, nsrc, ndst,
                                                  pw1, pb1, pw2, pb2, out);
}

// round 12
// speedup vs baseline: 1.6371x; 1.0438x over previous
#include <cuda_runtime.h>
#include <cuda_fp16.h>
#include <stdint.h>

// Problem constants
#define N_SRC0 200000
#define N_DST0 50000
#define N_DST1 10000
#define NE0    800000
#define NE1    160000
#define DIM    256
#define NBASE  4
#define BD     64
#define NPAIR  5000
#define NPTOT  (2 * NPAIR)

#define SCAN_CHUNK 4096
#define NBLK0 ((N_DST0 + SCAN_CHUNK - 1) / SCAN_CHUNK)   // 13
#define NBLK1 ((N_DST1 + SCAN_CHUNK - 1) / SCAN_CHUNK)   // 3
#define NBLKS (NBLK0 + NBLK1)                            // 16

#define NEDGE_BLK ((NE0 + NE1 + 255) / 256)              // 3750
#define NCVT_TOT  ((N_SRC0 * (DIM / 8)) / 256)           // 25000
#define NCVT_H    (NCVT_TOT / 2)

// ---------------------------------------------------------------------------
// Scratch
// ---------------------------------------------------------------------------
__device__ __align__(16) __half g_agg0h[(size_t)N_DST0 * DIM];
__device__ __align__(16) __half g_agg1h[(size_t)N_DST1 * DIM];
__device__ __align__(16) __half g_h0h[(size_t)N_DST0 * DIM];
__device__ float  g_h1[(size_t)N_DST1 * DIM];
__device__ __align__(16) __half g_xh[(size_t)N_SRC0 * DIM];

// fp16 weights (converted once per call in zero_kernel)
__device__ __align__(16) __half g_lw0h[DIM * DIM];
__device__ __align__(16) __half g_lw1h[DIM * DIM];
__device__ __align__(16) __half g_w0h[NBASE * BD * BD];
__device__ __align__(16) __half g_w1h[NBASE * BD * BD];

__device__ __align__(16) int g_cnt0[N_DST0];
__device__ __align__(16) int g_cnt1[N_DST1];
__device__ __align__(16) int g_rowptr0[N_DST0 + 1];
__device__ __align__(16) int g_rowptr1[N_DST1 + 1];
__device__ __align__(16) int g_cur0[N_DST0];
__device__ __align__(16) int g_cur1[N_DST1];
__device__ int g_esrc0[NE0];
__device__ int g_esrc1[NE1];
__device__ int g_part[NBLKS];
__device__ int g_flag[NBLKS];

// ---------------------------------------------------------------------------
// cp.async helpers
// ---------------------------------------------------------------------------
__device__ __forceinline__ void cp16(uint32_t dst, const void* src, int bytes) {
    asm volatile("cp.async.cg.shared.global [%0], [%1], 16, %2;\n"
                 :: "r"(dst), "l"(src), "r"(bytes));
}
__device__ __forceinline__ void cp_commit() {
    asm volatile("cp.async.commit_group;\n");
}
template <int N>
__device__ __forceinline__ void cp_wait() {
    asm volatile("cp.async.wait_group %0;\n" :: "n"(N));
}

// ---------------------------------------------------------------------------
// Convert helper (x fp32 -> g_xh fp16), one block = 2048 floats
// ---------------------------------------------------------------------------
__device__ __forceinline__ void convert_block(const float* __restrict__ x,
                                              size_t blk) {
    size_t i = blk * 256 + threadIdx.x;
    const float4* x4 = (const float4*)x;
    float4 a = x4[2 * i];
    float4 b = x4[2 * i + 1];
    __half2 h0 = __floats2half2_rn(a.x, a.y);
    __half2 h1 = __floats2half2_rn(a.z, a.w);
    __half2 h2 = __floats2half2_rn(b.x, b.y);
    __half2 h3 = __floats2half2_rn(b.z, b.w);
    uint4 o;
    o.x = *(uint32_t*)&h0; o.y = *(uint32_t*)&h1;
    o.z = *(uint32_t*)&h2; o.w = *(uint32_t*)&h3;
    ((uint4*)g_xh)[i] = o;
}

// ---------------------------------------------------------------------------
// Zero counters + scan flags, convert weights to fp16
// ---------------------------------------------------------------------------
__global__ void zero_kernel(const float* __restrict__ loop0,
                            const float* __restrict__ W0,
                            const float* __restrict__ loop1,
                            const float* __restrict__ W1) {
    int stride = gridDim.x * blockDim.x;
    int i0 = blockIdx.x * blockDim.x + threadIdx.x;
    for (int i = i0; i < N_DST0; i += stride) g_cnt0[i] = 0;
    for (int i = i0; i < N_DST1; i += stride) g_cnt1[i] = 0;
    if (i0 < NBLKS) g_flag[i0] = 0;
    // weight conversion (half2 pairs)
    for (int i = i0; i < DIM * DIM / 2; i += stride) {
        float2 v = ((const float2*)loop0)[i];
        ((__half2*)g_lw0h)[i] = __floats2half2_rn(v.x, v.y);
        float2 u = ((const float2*)loop1)[i];
        ((__half2*)g_lw1h)[i] = __floats2half2_rn(u.x, u.y);
    }
    for (int i = i0; i < NBASE * BD * BD / 2; i += stride) {
        float2 v = ((const float2*)W0)[i];
        ((__half2*)g_w0h)[i] = __floats2half2_rn(v.x, v.y);
        float2 u = ((const float2*)W1)[i];
        ((__half2*)g_w1h)[i] = __floats2half2_rn(u.x, u.y);
    }
}

// ---------------------------------------------------------------------------
// Fused: edge counting + first half of x conversion
// ---------------------------------------------------------------------------
__global__ __launch_bounds__(256) void count_convert_kernel(
    const float* __restrict__ x,
    const int*   __restrict__ dst0,
    const int*   __restrict__ dst1)
{
    int bid = blockIdx.x;
    if (bid < NEDGE_BLK) {
        int e = bid * 256 + threadIdx.x;
        if (e < NE0)            atomicAdd(&g_cnt0[dst0[e]], 1);
        else if (e < NE0 + NE1) atomicAdd(&g_cnt1[dst1[e - NE0]], 1);
    } else {
        convert_block(x, (size_t)(bid - NEDGE_BLK));
    }
}

// ---------------------------------------------------------------------------
// Single-launch scan with decoupled lookback (16 blocks, all resident).
// ---------------------------------------------------------------------------
__global__ __launch_bounds__(512) void scan_kernel() {
    const int* cnt; int* rowptr; int* cur; int n, nblk, b, gb, segbase;
    gb = blockIdx.x;
    if (gb < NBLK0) {
        cnt = g_cnt0; rowptr = g_rowptr0; cur = g_cur0;
        n = N_DST0; nblk = NBLK0; b = gb; segbase = 0;
    } else {
        cnt = g_cnt1; rowptr = g_rowptr1; cur = g_cur1;
        n = N_DST1; nblk = NBLK1; b = gb - NBLK0; segbase = NBLK0;
    }

    __shared__ int wsum[16];
    __shared__ int s_off;
    const int tid  = threadIdx.x;
    const int lane = tid & 31;
    const int wid  = tid >> 5;
    const int idx0 = b * SCAN_CHUNK + tid * 8;

    int v[8];
    if (idx0 + 8 <= n) {
        int4 a = *(const int4*)(cnt + idx0);
        int4 c = *(const int4*)(cnt + idx0 + 4);
        v[0]=a.x; v[1]=a.y; v[2]=a.z; v[3]=a.w;
        v[4]=c.x; v[5]=c.y; v[6]=c.z; v[7]=c.w;
    } else {
        #pragma unroll
        for (int j = 0; j < 8; ++j) v[j] = (idx0 + j < n) ? cnt[idx0 + j] : 0;
    }
    int incl[8]; int tot = 0;
    #pragma unroll
    for (int j = 0; j < 8; ++j) { tot += v[j]; incl[j] = tot; }

    int wincl = tot;
    #pragma unroll
    for (int o = 1; o < 32; o <<= 1) {
        int t = __shfl_up_sync(0xFFFFFFFFu, wincl, o);
        if (lane >= o) wincl += t;
    }
    if (lane == 31) wsum[wid] = wincl;
    __syncthreads();
    if (tid == 0) {
        int running = 0;
        #pragma unroll
        for (int w = 0; w < 16; ++w) { int t = wsum[w]; wsum[w] = running; running += t; }
        g_part[gb] = running;
        __threadfence();
        atomicExch(&g_flag[gb], 1);
        // lookback over predecessors in this segment
        int off = 0;
        for (int k = segbase; k < gb; ++k) {
            while (atomicAdd(&g_flag[k], 0) == 0) { }
            off += *((volatile int*)&g_part[k]);
        }
        s_off = off;
    }
    __syncthreads();

    int off = s_off;
    int myexcl = off + wsum[wid] + (wincl - tot);
    if (idx0 + 8 <= n) {
        int4 r0 = make_int4(myexcl + incl[0]-v[0], myexcl + incl[1]-v[1],
                            myexcl + incl[2]-v[2], myexcl + incl[3]-v[3]);
        int4 r1 = make_int4(myexcl + incl[4]-v[4], myexcl + incl[5]-v[5],
                            myexcl + incl[6]-v[6], myexcl + incl[7]-v[7]);
        *(int4*)(rowptr + idx0)     = r0;
        *(int4*)(rowptr + idx0 + 4) = r1;
        *(int4*)(cur + idx0)        = r0;
        *(int4*)(cur + idx0 + 4)    = r1;
    } else {
        #pragma unroll
        for (int j = 0; j < 8; ++j)
            if (idx0 + j < n) {
                int e = myexcl + incl[j] - v[j];
                rowptr[idx0 + j] = e;
                cur[idx0 + j] = e;
            }
    }
    if (b == nblk - 1 && tid == 0) rowptr[n] = off + g_part[gb];
}

// ---------------------------------------------------------------------------
// Fused: CSR fill + second half of x conversion
// ---------------------------------------------------------------------------
__global__ __launch_bounds__(256) void fill_convert_kernel(
    const float* __restrict__ x,
    const int* __restrict__ src0, const int* __restrict__ dst0,
    const int* __restrict__ src1, const int* __restrict__ dst1)
{
    int bid = blockIdx.x;
    if (bid < NEDGE_BLK) {
        int e = bid * 256 + threadIdx.x;
        if (e < NE0) {
            int p = atomicAdd(&g_cur0[dst0[e]], 1);
            g_esrc0[p] = src0[e];
        } else if (e < NE0 + NE1) {
            int e1 = e - NE0;
            int p = atomicAdd(&g_cur1[dst1[e1]], 1);
            g_esrc1[p] = src1[e1];
        }
    } else {
        convert_block(x, (size_t)(bid - NEDGE_BLK) + NCVT_H);
    }
}

// ---------------------------------------------------------------------------
// Pull gather (fp16 -> fp16 agg, fp32 accumulation). 32 threads/row.
// ---------------------------------------------------------------------------
template <int WHICH>
__global__ __launch_bounds__(128) void gather_kernel() {
    const __half* feat = WHICH ? g_h0h : g_xh;
    __half* agg        = WHICH ? g_agg1h : g_agg0h;
    const int* rowptr  = WHICH ? g_rowptr1 : g_rowptr0;
    const int* esrc    = WHICH ? g_esrc1 : g_esrc0;
    const int ndst     = WHICH ? N_DST1 : N_DST0;

    int d = blockIdx.x * 4 + (threadIdx.x >> 5);
    int lane = threadIdx.x & 31;
    if (d >= ndst) return;

    int beg = rowptr[d], end = rowptr[d + 1];
    float a0=0.f,a1=0.f,a2=0.f,a3=0.f,a4=0.f,a5=0.f,a6=0.f,a7=0.f;
    const uint4* f16 = (const uint4*)feat;

    #define ACCUM(v) do {                                           \
        float2 _f;                                                  \
        _f = __half22float2(*(__half2*)&(v).x); a0 += _f.x; a1 += _f.y; \
        _f = __half22float2(*(__half2*)&(v).y); a2 += _f.x; a3 += _f.y; \
        _f = __half22float2(*(__half2*)&(v).z); a4 += _f.x; a5 += _f.y; \
        _f = __half22float2(*(__half2*)&(v).w); a6 += _f.x; a7 += _f.y; \
    } while (0)

    int i = beg;
    for (; i + 3 < end; i += 4) {
        int s0 = esrc[i], s1 = esrc[i + 1], s2 = esrc[i + 2], s3 = esrc[i + 3];
        uint4 v0 = f16[(size_t)s0 * 32 + lane];
        uint4 v1 = f16[(size_t)s1 * 32 + lane];
        uint4 v2 = f16[(size_t)s2 * 32 + lane];
        uint4 v3 = f16[(size_t)s3 * 32 + lane];
        ACCUM(v0); ACCUM(v1); ACCUM(v2); ACCUM(v3);
    }
    for (; i < end; ++i) {
        int s0 = esrc[i];
        uint4 v0 = f16[(size_t)s0 * 32 + lane];
        ACCUM(v0);
    }
    #undef ACCUM

    __half2 o0 = __floats2half2_rn(a0, a1);
    __half2 o1 = __floats2half2_rn(a2, a3);
    __half2 o2 = __floats2half2_rn(a4, a5);
    __half2 o3 = __floats2half2_rn(a6, a7);
    uint4 ov;
    ov.x = *(uint32_t*)&o0; ov.y = *(uint32_t*)&o1;
    ov.z = *(uint32_t*)&o2; ov.w = *(uint32_t*)&o3;
    ((uint4*)agg)[(size_t)d * 32 + lane] = ov;
}

// ---------------------------------------------------------------------------
// fp16 tensor-core fused layer GEMM, double-buffered cp.async pipeline.
// All operands fp16 in gmem (xdh/aggh features, pre-converted weights).
// ---------------------------------------------------------------------------
__device__ __forceinline__ __half2 f2h2(float a, float b) {
    return __floats2half2_rn(a, b);
}

template <int LAYER>
__global__ __launch_bounds__(256) void layer_kernel(
    const float* __restrict__ bias,   // [256] fp32
    float*       __restrict__ out2,   // layer1: mirror to d_out region
    int M)
{
    const __half* aggh = (LAYER == 0) ? g_agg0h : g_agg1h;
    const __half* xdh  = (LAYER == 0) ? g_xh   : g_h0h;
    const __half* lw   = (LAYER == 0) ? g_lw0h : g_lw1h;
    const __half* wbd  = (LAYER == 0) ? g_w0h  : g_w1h;

    __shared__ __half As[2][128][40];   // 2-stage, pad 40 (80B row, 16B-mult)
    __shared__ __half Bs[2][32][72];    // 2-stage, pad 72 (144B row, 16B-mult)

    const int cb  = blockIdx.x;
    const int r0  = blockIdx.y * 128;
    const int tid = threadIdx.x;
    const int lane = tid & 31;
    const int w   = tid >> 5;
    const int wm  = w & 3;
    const int wn  = w >> 2;
    const int t4  = lane >> 2;
    const int tc  = lane & 3;

    // cp.async destination addresses (fixed per thread, per stage)
    const int arow0 = tid >> 2,       aq0 = tid & 3;          // l=0
    const int arow1 = (tid + 256) >> 2, aq1 = (tid + 256) & 3; // l=1
    const int bk = tid >> 3, bq = tid & 7;
    uint32_t asA[2], asA2[2], asB[2];
    #pragma unroll
    for (int s = 0; s < 2; ++s) {
        asA[s]  = (uint32_t)__cvta_generic_to_shared(&As[s][arow0][aq0 * 8]);
        asA2[s] = (uint32_t)__cvta_generic_to_shared(&As[s][arow1][aq1 * 8]);
        asB[s]  = (uint32_t)__cvta_generic_to_shared(&Bs[s][bk][bq * 8]);
    }

    float acc[2][4][4];
    #pragma unroll
    for (int mt = 0; mt < 2; ++mt)
        #pragma unroll
        for (int nt = 0; nt < 4; ++nt)
            #pragma unroll
            for (int i = 0; i < 4; ++i) acc[mt][nt][i] = 0.f;

    // issue loads for chunk ch into stage buf
    auto issue = [&](int ch, int buf) {
        const int akbase = (ch < 8) ? ch * 32 : cb * 64 + (ch - 8) * 32;
        const __half* amat = (ch < 8) ? xdh : aggh;
        int r = r0 + arow0;
        cp16(asA[buf],
             amat + (size_t)(r < M ? r : 0) * DIM + akbase + aq0 * 8,
             r < M ? 16 : 0);
        r = r0 + arow1;
        cp16(asA2[buf],
             amat + (size_t)(r < M ? r : 0) * DIM + akbase + aq1 * 8,
             r < M ? 16 : 0);
        const __half* bsrc = (ch < 8)
            ? lw + (size_t)(ch * 32 + bk) * DIM + cb * 64 + bq * 8
            : wbd + (size_t)cb * BD * BD + (size_t)((ch - 8) * 32 + bk) * BD + bq * 8;
        cp16(asB[buf], bsrc, 16);
        cp_commit();
    };

    issue(0, 0);
    for (int ch = 0; ch < 10; ++ch) {
        const int buf = ch & 1;
        if (ch < 9) issue(ch + 1, buf ^ 1);
        // wait for chunk ch's loads (allow the just-issued group to fly)
        if (ch < 9) cp_wait<1>(); else cp_wait<0>();
        __syncthreads();

        const __half (*A)[40] = As[buf];
        const __half (*B)[72] = Bs[buf];
        #pragma unroll
        for (int ks = 0; ks < 2; ++ks) {
            const int kb = ks * 16;
            uint32_t a[2][4];
            #pragma unroll
            for (int mt = 0; mt < 2; ++mt) {
                int mrow = wm * 32 + mt * 16 + t4;
                a[mt][0] = *(const uint32_t*)&A[mrow][kb + 2 * tc];
                a[mt][1] = *(const uint32_t*)&A[mrow + 8][kb + 2 * tc];
                a[mt][2] = *(const uint32_t*)&A[mrow][kb + 2 * tc + 8];
                a[mt][3] = *(const uint32_t*)&A[mrow + 8][kb + 2 * tc + 8];
            }
            #pragma unroll
            for (int nt = 0; nt < 4; ++nt) {
                int ncol = wn * 32 + nt * 8 + t4;
                uint32_t b0 = (uint32_t)*(const uint16_t*)&B[kb + 2 * tc][ncol]
                            | ((uint32_t)*(const uint16_t*)&B[kb + 2 * tc + 1][ncol] << 16);
                uint32_t b1 = (uint32_t)*(const uint16_t*)&B[kb + 2 * tc + 8][ncol]
                            | ((uint32_t)*(const uint16_t*)&B[kb + 2 * tc + 9][ncol] << 16);
                #pragma unroll
                for (int mt = 0; mt < 2; ++mt) {
                    asm volatile(
                        "mma.sync.aligned.m16n8k16.row.col.f32.f16.f16.f32 "
                        "{%0,%1,%2,%3}, {%4,%5,%6,%7}, {%8,%9}, {%0,%1,%2,%3};\n"
                        : "+f"(acc[mt][nt][0]), "+f"(acc[mt][nt][1]),
                          "+f"(acc[mt][nt][2]), "+f"(acc[mt][nt][3])
                        : "r"(a[mt][0]), "r"(a[mt][1]), "r"(a[mt][2]), "r"(a[mt][3]),
                          "r"(b0), "r"(b1));
                }
            }
        }
        __syncthreads();   // compute(ch) done before stage buf is overwritten
    }

    // ---- epilogue: bias + relu ----
    #pragma unroll
    for (int nt = 0; nt < 4; ++nt) {
        int c = cb * 64 + wn * 32 + nt * 8 + 2 * tc;
        float2 bb = *(const float2*)(bias + c);
        #pragma unroll
        for (int mt = 0; mt < 2; ++mt) {
            int r = r0 + wm * 32 + mt * 16 + t4;
            float ox0 = fmaxf(acc[mt][nt][0] + bb.x, 0.f);
            float oy0 = fmaxf(acc[mt][nt][1] + bb.y, 0.f);
            float ox1 = fmaxf(acc[mt][nt][2] + bb.x, 0.f);
            float oy1 = fmaxf(acc[mt][nt][3] + bb.y, 0.f);
            if (LAYER == 0) {
                if (r < M)
                    *(__half2*)(g_h0h + (size_t)r * DIM + c) = f2h2(ox0, oy0);
                if (r + 8 < M)
                    *(__half2*)(g_h0h + (size_t)(r + 8) * DIM + c) = f2h2(ox1, oy1);
            } else {
                if (r < M) {
                    float2 o = make_float2(ox0, oy0);
                    *(float2*)(g_h1 + (size_t)r * DIM + c) = o;
                    *(float2*)(out2 + (size_t)r * DIM + c) = o;
                }
                if (r + 8 < M) {
                    float2 o = make_float2(ox1, oy1);
                    *(float2*)(g_h1 + (size_t)(r + 8) * DIM + c) = o;
                    *(float2*)(out2 + (size_t)(r + 8) * DIM + c) = o;
                }
            }
        }
    }
}

// ---------------------------------------------------------------------------
// Link predictor, batched: 32 pairs per 128-thread block.
// ---------------------------------------------------------------------------
#define PPB 32
__global__ __launch_bounds__(128) void pred_kernel(
    const int*   __restrict__ ps, const int* __restrict__ pd,
    const int*   __restrict__ ns, const int* __restrict__ nd,
    const float* __restrict__ pw1,    // [256, 128]
    const float* __restrict__ pb1,    // [128]
    const float* __restrict__ pw2,    // [128]
    const float* __restrict__ pb2,    // [1]
    float*       __restrict__ out)    // [10000]
{
    const float* h = g_h1;
    __shared__ float es[PPB][256];
    __shared__ int   sa[PPB], sb[PPB];
    __shared__ float s_part[4][PPB];

    int tid  = threadIdx.x;
    int lane = tid & 31;
    int wid  = tid >> 5;
    int pbase = blockIdx.x * PPB;

    if (tid < PPB) {
        int P = pbase + tid;
        int a = 0, b = 0;
        if (P < NPTOT) {
            if (P < NPAIR) { a = ps[P]; b = pd[P]; }
            else           { a = ns[P - NPAIR]; b = nd[P - NPAIR]; }
        }
        sa[tid] = a; sb[tid] = b;
    }
    __syncthreads();

    #pragma unroll 4
    for (int p = 0; p < PPB; ++p) {
        int a = sa[p], b = sb[p];
        es[p][tid]       = h[(size_t)a * DIM + tid]       * h[(size_t)b * DIM + tid];
        es[p][tid + 128] = h[(size_t)a * DIM + 128 + tid] * h[(size_t)b * DIM + 128 + tid];
    }
    __syncthreads();

    float acc[PPB];
    #pragma unroll
    for (int p = 0; p < PPB; ++p) acc[p] = 0.f;

    for (int j = 0; j < 256; j += 4) {
        float w0 = pw1[(j + 0) * 128 + tid];
        float w1 = pw1[(j + 1) * 128 + tid];
        float w2 = pw1[(j + 2) * 128 + tid];
        float w3 = pw1[(j + 3) * 128 + tid];
        #pragma unroll
        for (int p = 0; p < PPB; ++p) {
            float4 e4 = *(const float4*)&es[p][j];
            acc[p] += e4.x * w0 + e4.y * w1 + e4.z * w2 + e4.w * w3;
        }
    }

    float pb  = pb1[tid];
    float w2v = pw2[tid];
    #pragma unroll
    for (int p = 0; p < PPB; ++p) {
        float v = fmaxf(acc[p] + pb, 0.f) * w2v;
        #pragma unroll
        for (int o = 16; o; o >>= 1) v += __shfl_xor_sync(0xFFFFFFFFu, v, o);
        if (lane == 0) s_part[wid][p] = v;
    }
    __syncthreads();
    if (tid < PPB) {
        int P = pbase + tid;
        if (P < NPTOT)
            out[P] = s_part[0][tid] + s_part[1][tid] + s_part[2][tid] + s_part[3][tid]
                   + pb2[0];
    }
}

// ---------------------------------------------------------------------------
// Launch
// ---------------------------------------------------------------------------
extern "C" void kernel_launch(void* const* d_in, const int* in_sizes, int n_in,
                              void* d_out, int out_size)
{
    const float* x     = (const float*)d_in[0];
    const int*   src0  = (const int*)d_in[1];
    const int*   dst0  = (const int*)d_in[2];
    const int*   src1  = (const int*)d_in[3];
    const int*   dst1  = (const int*)d_in[4];
    const int*   psrc  = (const int*)d_in[5];
    const int*   pdst  = (const int*)d_in[6];
    const int*   nsrc  = (const int*)d_in[7];
    const int*   ndst  = (const int*)d_in[8];
    const float* W0    = (const float*)d_in[9];
    const float* loop0 = (const float*)d_in[10];
    const float* b0    = (const float*)d_in[11];
    const float* W1    = (const float*)d_in[12];
    const float* loop1 = (const float*)d_in[13];
    const float* b1    = (const float*)d_in[14];
    const float* pw1   = (const float*)d_in[15];
    const float* pb1   = (const float*)d_in[16];
    const float* pw2   = (const float*)d_in[17];
    const float* pb2   = (const float*)d_in[18];
    float*       out   = (float*)d_out;

    // zero counters/flags + fp16 weight staging
    zero_kernel<<<256, 256>>>(loop0, W0, loop1, W1);
    // CSR count fused with first convert half
    count_convert_kernel<<<NEDGE_BLK + NCVT_H, 256>>>(x, dst0, dst1);
    // single-launch lookback scan
    scan_kernel<<<NBLKS, 512>>>();
    // CSR fill fused with second convert half
    fill_convert_kernel<<<NEDGE_BLK + (NCVT_TOT - NCVT_H), 256>>>(
        x, src0, dst0, src1, dst1);

    // layer 0
    gather_kernel<0><<<(N_DST0 + 3) / 4, 128>>>();
    {
        dim3 grid(NBASE, (N_DST0 + 127) / 128);
        layer_kernel<0><<<grid, 256>>>(b0, nullptr, N_DST0);
    }

    // layer 1
    gather_kernel<1><<<(N_DST1 + 3) / 4, 128>>>();
    {
        dim3 grid(NBASE, (N_DST1 + 127) / 128);
        layer_kernel<1><<<grid, 256>>>(b1, out + NPTOT, N_DST1);
    }

    // link prediction
    pred_kernel<<<(NPTOT + PPB - 1) / PPB, 128>>>(psrc, pdst, nsrc, ndst,
                                                  pw1, pb1, pw2, pb2, out);
}